// round 1
// baseline (speedup 1.0000x reference)
#include <cuda_runtime.h>
#include <cuda_bf16.h>

#define N_NODES   50000
#define N_EDGES   800000
#define NUM_GRAPHS 500
#define CONV_OUT  128
#define HCAT      384   // 3 * 128
#define MAX_DIN   160

// ---------------- scratch (static device globals; no allocation) ----------------
__device__ float    d_hin[N_NODES * MAX_DIN];
__device__ float    d_projL[N_NODES * CONV_OUT];
__device__ float    d_projR[N_NODES * CONV_OUT];
__device__ float    d_agg[N_NODES * CONV_OUT];
__device__ float    d_h[N_NODES * CONV_OUT];
__device__ float    d_deg[N_NODES];
__device__ unsigned d_genc[NUM_GRAPHS * HCAT];
__device__ float    d_Wcat[MAX_DIN * 256];

// monotone float <-> uint encoding for atomicMax on signed floats
__device__ __forceinline__ unsigned encf(float f) {
    unsigned u = __float_as_uint(f);
    return (u & 0x80000000u) ? ~u : (u | 0x80000000u);
}
__device__ __forceinline__ float decf(unsigned u) {
    u = (u & 0x80000000u) ? (u & 0x7FFFFFFFu) : ~u;
    return __uint_as_float(u);
}
#define ENC_NEG_INF 0x007FFFFFu   // encf(-inf)

// ---------------- kernels ----------------

__global__ void init_kernel() {
    int i = blockIdx.x * blockDim.x + threadIdx.x;
    if (i < N_NODES) d_deg[i] = 0.f;
    if (i < NUM_GRAPHS * HCAT) d_genc[i] = ENC_NEG_INF;
}

__global__ void deg_kernel(const int* __restrict__ dst) {
    int e = blockIdx.x * blockDim.x + threadIdx.x;
    if (e < N_EDGES) atomicAdd(&d_deg[dst[e]], 1.0f);
}

// pack Wl [K,128] and Wr [K,128] into Wcat [K,256]
__global__ void pack_w(const float* __restrict__ Wl, const float* __restrict__ Wr, int K) {
    int i = blockIdx.x * blockDim.x + threadIdx.x;
    if (i < K * 128) {
        int k = i / 128, c = i % 128;
        d_Wcat[k * 256 + c]       = Wl[i];
        d_Wcat[k * 256 + 128 + c] = Wr[i];
    }
}

// hin[i] = concat(hprev[i] (dh dims), info[batch[i]] (32 dims))
__global__ void build_hin(const float* __restrict__ hprev, const float* __restrict__ info,
                          const int* __restrict__ batch, int dh) {
    int din = dh + 32;
    long long i = (long long)blockIdx.x * blockDim.x + threadIdx.x;
    long long total = (long long)N_NODES * din;
    if (i < total) {
        int node = (int)(i / din);
        int c    = (int)(i % din);
        d_hin[i] = (c < dh) ? hprev[(long long)node * dh + c]
                            : info[batch[node] * 32 + (c - dh)];
    }
}

__global__ void zero_agg() {
    int i = blockIdx.x * blockDim.x + threadIdx.x;
    if (i < N_NODES * CONV_OUT) d_agg[i] = 0.f;
}

// C[M,256] = A[M,K] @ Wcat[K,256]; cols 0..127 -> projL, 128..255 -> projR
// 64x64 tile, 256 threads, 4x4 micro-tile, TK=16
__global__ void gemm_kernel(const float* __restrict__ A, int M, int K) {
    __shared__ float As[16][65];
    __shared__ float Bs[16][64];

    int bm = blockIdx.x * 64;
    int bn = blockIdx.y * 64;
    int tid = threadIdx.x;
    int tr = tid / 16, tc = tid % 16;

    float acc[4][4];
#pragma unroll
    for (int i = 0; i < 4; i++)
#pragma unroll
        for (int j = 0; j < 4; j++) acc[i][j] = 0.f;

    for (int k0 = 0; k0 < K; k0 += 16) {
        // load A tile: 64 rows x 16 k
#pragma unroll
        for (int i = 0; i < 4; i++) {
            int idx = tid + i * 256;       // 0..1023
            int m = idx >> 4, k = idx & 15;
            int row = bm + m;
            As[k][m] = (row < M) ? A[(long long)row * K + (k0 + k)] : 0.f;
        }
        // load B tile: 16 k x 64 cols
#pragma unroll
        for (int i = 0; i < 4; i++) {
            int idx = tid + i * 256;
            int k = idx >> 6, n = idx & 63;
            Bs[k][n] = d_Wcat[(k0 + k) * 256 + bn + n];
        }
        __syncthreads();

#pragma unroll
        for (int k = 0; k < 16; k++) {
            float a[4], b[4];
#pragma unroll
            for (int i = 0; i < 4; i++) a[i] = As[k][tr * 4 + i];
#pragma unroll
            for (int j = 0; j < 4; j++) b[j] = Bs[k][tc * 4 + j];
#pragma unroll
            for (int i = 0; i < 4; i++)
#pragma unroll
                for (int j = 0; j < 4; j++) acc[i][j] += a[i] * b[j];
        }
        __syncthreads();
    }

#pragma unroll
    for (int i = 0; i < 4; i++) {
        int row = bm + tr * 4 + i;
        if (row >= M) continue;
#pragma unroll
        for (int j = 0; j < 4; j++) {
            int col = bn + tc * 4 + j;
            if (col < 128) d_projL[(long long)row * 128 + col] = acc[i][j];
            else           d_projR[(long long)row * 128 + (col - 128)] = acc[i][j];
        }
    }
}

// scatter: agg[dst] += projL[src]  (thread = edge x 4-float group)
__global__ void scatter_kernel(const int* __restrict__ src, const int* __restrict__ dst) {
    long long t = (long long)blockIdx.x * blockDim.x + threadIdx.x;
    int e = (int)(t >> 5);
    int g = (int)(t & 31);
    if (e < N_EDGES) {
        int s = src[e], d = dst[e];
        float4 v = *(const float4*)(&d_projL[(long long)s * 128 + g * 4]);
        float* a = &d_agg[(long long)d * 128 + g * 4];
        atomicAdd(a + 0, v.x);
        atomicAdd(a + 1, v.y);
        atomicAdd(a + 2, v.z);
        atomicAdd(a + 3, v.w);
    }
}

// h = agg/deg + projR + b ; update per-graph max (encoded)
__global__ void combine_kernel(const float* __restrict__ b, const int* __restrict__ batch, int layer) {
    int t = blockIdx.x * blockDim.x + threadIdx.x;
    if (t < N_NODES * CONV_OUT) {
        int i = t >> 7, f = t & 127;
        float val = d_agg[t] / fmaxf(d_deg[i], 1.0f) + d_projR[t] + b[f];
        d_h[t] = val;
        atomicMax(&d_genc[batch[i] * HCAT + layer * 128 + f], encf(val));
    }
}

// per-graph: g[384] -> z=relu(g@Wfc1+bfc1) [160] -> out = z@Wfc2+bfc2 [10]
__global__ void fc_kernel(const float* __restrict__ Wfc1, const float* __restrict__ bfc1,
                          const float* __restrict__ Wfc2, const float* __restrict__ bfc2,
                          float* __restrict__ out) {
    __shared__ float g[HCAT];
    __shared__ float z[160];
    int gr = blockIdx.x, t = threadIdx.x;  // 160 threads

    for (int i = t; i < HCAT; i += 160) g[i] = decf(d_genc[gr * HCAT + i]);
    __syncthreads();

    float acc = bfc1[t];
#pragma unroll 8
    for (int k = 0; k < HCAT; k++) acc += g[k] * Wfc1[k * 160 + t];
    z[t] = fmaxf(acc, 0.f);
    __syncthreads();

    if (t < 10) {
        float o = bfc2[t];
#pragma unroll 8
        for (int k = 0; k < 160; k++) o += z[k] * Wfc2[k * 10 + t];
        out[gr * 10 + t] = o;
    }
}

// ---------------- launch ----------------

extern "C" void kernel_launch(void* const* d_in, const int* in_sizes, int n_in,
                              void* d_out, int out_size) {
    const float* x     = (const float*)d_in[0];
    const int*   eidx  = (const int*)d_in[1];       // [2, E] row-major
    const int*   batch = (const int*)d_in[2];
    const float* info  = (const float*)d_in[3];
    const float* Wl[3] = { (const float*)d_in[4], (const float*)d_in[7],  (const float*)d_in[10] };
    const float* Wr[3] = { (const float*)d_in[5], (const float*)d_in[8],  (const float*)d_in[11] };
    const float* bb[3] = { (const float*)d_in[6], (const float*)d_in[9],  (const float*)d_in[12] };
    const float* Wfc1  = (const float*)d_in[13];
    const float* bfc1  = (const float*)d_in[14];
    const float* Wfc2  = (const float*)d_in[15];
    const float* bfc2  = (const float*)d_in[16];
    float* out = (float*)d_out;

    const int* src = eidx;
    const int* dst = eidx + N_EDGES;

    const int T = 256;

    // init deg + pool-max buffers
    {
        int n = NUM_GRAPHS * HCAT;  // 192000 > N_NODES
        init_kernel<<<(n + T - 1) / T, T>>>();
    }
    deg_kernel<<<(N_EDGES + T - 1) / T, T>>>(dst);

    int dh_arr[3]  = { 96, 128, 128 };     // prev-h width
    int din_arr[3] = { 128, 160, 160 };

    for (int layer = 0; layer < 3; layer++) {
        int dh = dh_arr[layer], din = din_arr[layer];
        const float* hprev = (layer == 0) ? x : nullptr;  // layer>0 uses d_h inside kernel via pointer

        pack_w<<<(din * 128 + T - 1) / T, T>>>(Wl[layer], Wr[layer], din);

        {
            long long total = (long long)N_NODES * din;
            // for layer>0 we need a device pointer to d_h; get it via cudaGetSymbolAddress is
            // allocation-free and host-side (outside capture restrictions it's fine, but to be
            // strictly capture-safe we resolve it every call — it's just an address lookup).
            if (layer == 0) {
                build_hin<<<(int)((total + T - 1) / T), T>>>(x, info, batch, dh);
            } else {
                static float* hptr = nullptr;
                if (!hptr) cudaGetSymbolAddress((void**)&hptr, d_h);
                build_hin<<<(int)((total + T - 1) / T), T>>>(hptr, info, batch, dh);
            }
            (void)hprev;
        }

        gemm_kernel<<<dim3((N_NODES + 63) / 64, 4), 256>>>(
            // read d_hin via symbol address
            [](){ static float* p = nullptr; if (!p) cudaGetSymbolAddress((void**)&p, d_hin); return p; }(),
            N_NODES, din);

        zero_agg<<<(N_NODES * CONV_OUT + T - 1) / T, T>>>();

        {
            long long tthreads = (long long)N_EDGES * 32;
            scatter_kernel<<<(int)((tthreads + T - 1) / T), T>>>(src, dst);
        }

        combine_kernel<<<(N_NODES * CONV_OUT + T - 1) / T, T>>>(bb[layer], batch, layer);
    }

    fc_kernel<<<NUM_GRAPHS, 160>>>(Wfc1, bfc1, Wfc2, bfc2, out);
    (void)in_sizes; (void)n_in; (void)out_size;
}

// round 2
// speedup vs baseline: 1.8372x; 1.8372x over previous
#include <cuda_runtime.h>
#include <cuda_bf16.h>

#define N_NODES    50000
#define N_EDGES    800000
#define NUM_GRAPHS 500
#define CONV_OUT   128
#define HCAT       384   // 3 * 128
#define MAX_DIN    160

// ---------------- scratch (static device globals; no allocation) ----------------
__device__ float    d_projL[N_NODES * CONV_OUT];
__device__ float    d_projR[N_NODES * CONV_OUT];
__device__ float    d_h[N_NODES * CONV_OUT];
__device__ int      d_count[N_NODES];
__device__ int      d_rowptr[N_NODES + 1];
__device__ int      d_cursor[N_NODES];
__device__ int      d_adj[N_EDGES];
__device__ unsigned d_genc[NUM_GRAPHS * HCAT];
__device__ float    d_Wcat[MAX_DIN * 256];

// monotone float <-> uint encoding for atomicMax on signed floats
__device__ __forceinline__ unsigned encf(float f) {
    unsigned u = __float_as_uint(f);
    return (u & 0x80000000u) ? ~u : (u | 0x80000000u);
}
__device__ __forceinline__ float decf(unsigned u) {
    u = (u & 0x80000000u) ? (u & 0x7FFFFFFFu) : ~u;
    return __uint_as_float(u);
}
#define ENC_NEG_INF 0x007FFFFFu   // encf(-inf)

// ---------------- kernels ----------------

// zero count + init pool-max encodings
__global__ void init_kernel() {
    int i = blockIdx.x * blockDim.x + threadIdx.x;
    if (i < N_NODES) d_count[i] = 0;
    if (i < NUM_GRAPHS * HCAT) d_genc[i] = ENC_NEG_INF;
}

__global__ void deg_kernel(const int* __restrict__ dst) {
    int e = blockIdx.x * blockDim.x + threadIdx.x;
    if (e < N_EDGES) atomicAdd(&d_count[dst[e]], 1);
}

// single-block exclusive scan over d_count -> d_rowptr, d_cursor
__global__ void scan_kernel() {
    __shared__ int s[1024];
    int t = threadIdx.x;
    const int CH = (N_NODES + 1023) / 1024;   // 49
    int base = t * CH;
    int lim = min(base + CH, N_NODES);
    int sum = 0;
    for (int i = base; i < lim; i++) sum += d_count[i];
    s[t] = sum;
    __syncthreads();
    // inclusive scan (Hillis-Steele)
    for (int off = 1; off < 1024; off <<= 1) {
        int v = (t >= off) ? s[t - off] : 0;
        __syncthreads();
        s[t] += v;
        __syncthreads();
    }
    int run = s[t] - sum;   // exclusive prefix for this chunk
    for (int i = base; i < lim; i++) {
        d_rowptr[i] = run;
        d_cursor[i] = run;
        run += d_count[i];
    }
    if (t == 1023) d_rowptr[N_NODES] = s[1023];
}

__global__ void fill_kernel(const int* __restrict__ src, const int* __restrict__ dst) {
    int e = blockIdx.x * blockDim.x + threadIdx.x;
    if (e < N_EDGES) {
        int d = dst[e];
        int pos = atomicAdd(&d_cursor[d], 1);
        d_adj[pos] = src[e];
    }
}

// pack Wl [K,128] and Wr [K,128] into Wcat [K,256]
__global__ void pack_w(const float* __restrict__ Wl, const float* __restrict__ Wr, int K) {
    int i = blockIdx.x * blockDim.x + threadIdx.x;
    if (i < K * 128) {
        int k = i / 128, c = i % 128;
        d_Wcat[k * 256 + c]       = Wl[i];
        d_Wcat[k * 256 + 128 + c] = Wr[i];
    }
}

// C[M,256] = concat(h, info[batch]) [M,K] @ Wcat[K,256]
// cols 0..127 -> projL, 128..255 -> projR
// 64x64 tile, 256 threads, 4x4 micro-tile, TK=16, float4 smem reads
__global__ void gemm_kernel(const float* __restrict__ hsrc, int dh,
                            const float* __restrict__ info,
                            const int* __restrict__ batch, int K) {
    __shared__ float As[16][68];   // padded: 272B row stride, 16B aligned
    __shared__ float Bs[16][64];
    __shared__ int   sb[64];

    const int M = N_NODES;
    int bm = blockIdx.x * 64;
    int bn = blockIdx.y * 64;
    int tid = threadIdx.x;
    int tr = tid >> 4, tc = tid & 15;

    if (tid < 64) {
        int row = bm + tid;
        sb[tid] = (row < M) ? batch[row] : 0;
    }

    float acc[4][4];
#pragma unroll
    for (int i = 0; i < 4; i++)
#pragma unroll
        for (int j = 0; j < 4; j++) acc[i][j] = 0.f;

    __syncthreads();

    for (int k0 = 0; k0 < K; k0 += 16) {
        // A tile: 64 rows x 16 k, fused concat(h, info[batch])
#pragma unroll
        for (int i = 0; i < 4; i++) {
            int idx = tid + i * 256;
            int m = idx >> 4, k = idx & 15;
            int row = bm + m;
            int col = k0 + k;
            float v = 0.f;
            if (row < M) {
                v = (col < dh) ? hsrc[(size_t)row * dh + col]
                               : info[sb[m] * 32 + (col - dh)];
            }
            As[k][m] = v;
        }
        // B tile: 16 k x 64 cols
#pragma unroll
        for (int i = 0; i < 4; i++) {
            int idx = tid + i * 256;
            int k = idx >> 6, n = idx & 63;
            Bs[k][n] = d_Wcat[(k0 + k) * 256 + bn + n];
        }
        __syncthreads();

#pragma unroll
        for (int k = 0; k < 16; k++) {
            float4 av = *(const float4*)&As[k][tr * 4];
            float4 bv = *(const float4*)&Bs[k][tc * 4];
            float a[4] = { av.x, av.y, av.z, av.w };
            float b[4] = { bv.x, bv.y, bv.z, bv.w };
#pragma unroll
            for (int i = 0; i < 4; i++)
#pragma unroll
                for (int j = 0; j < 4; j++) acc[i][j] += a[i] * b[j];
        }
        __syncthreads();
    }

    bool left = (bn < 128);
    int cbase = left ? bn : (bn - 128);
#pragma unroll
    for (int i = 0; i < 4; i++) {
        int row = bm + tr * 4 + i;
        if (row >= M) continue;
        float4 o = make_float4(acc[i][0], acc[i][1], acc[i][2], acc[i][3]);
        size_t off = (size_t)row * 128 + cbase + tc * 4;
        if (left) *(float4*)&d_projL[off] = o;
        else      *(float4*)&d_projR[off] = o;
    }
}

// one warp per node: h = mean(projL[neighbors]) + projR + b ; pool max
__global__ void gather_combine(const float* __restrict__ b,
                               const int* __restrict__ batch, int layer) {
    int warp = (blockIdx.x * blockDim.x + threadIdx.x) >> 5;
    int lane = threadIdx.x & 31;
    if (warp >= N_NODES) return;

    int s0 = d_rowptr[warp];
    int s1 = d_rowptr[warp + 1];

    float4 acc = make_float4(0.f, 0.f, 0.f, 0.f);
#pragma unroll 4
    for (int j = s0; j < s1; j++) {
        int nb = d_adj[j];
        float4 v = *(const float4*)&d_projL[(size_t)nb * 128 + lane * 4];
        acc.x += v.x; acc.y += v.y; acc.z += v.z; acc.w += v.w;
    }
    float degf = fmaxf((float)(s1 - s0), 1.0f);
    float inv = 1.0f / degf;
    float4 r  = *(const float4*)&d_projR[(size_t)warp * 128 + lane * 4];
    float4 bb = *(const float4*)&b[lane * 4];
    float4 hv;
    hv.x = acc.x * inv + r.x + bb.x;
    hv.y = acc.y * inv + r.y + bb.y;
    hv.z = acc.z * inv + r.z + bb.z;
    hv.w = acc.w * inv + r.w + bb.w;
    *(float4*)&d_h[(size_t)warp * 128 + lane * 4] = hv;

    unsigned* g = &d_genc[batch[warp] * HCAT + layer * 128 + lane * 4];
    atomicMax(g + 0, encf(hv.x));
    atomicMax(g + 1, encf(hv.y));
    atomicMax(g + 2, encf(hv.z));
    atomicMax(g + 3, encf(hv.w));
}

// per-graph: g[384] -> z=relu(g@Wfc1+bfc1) [160] -> out = z@Wfc2+bfc2 [10]
__global__ void fc_kernel(const float* __restrict__ Wfc1, const float* __restrict__ bfc1,
                          const float* __restrict__ Wfc2, const float* __restrict__ bfc2,
                          float* __restrict__ out) {
    __shared__ float g[HCAT];
    __shared__ float z[160];
    int gr = blockIdx.x, t = threadIdx.x;  // 160 threads

    for (int i = t; i < HCAT; i += 160) g[i] = decf(d_genc[gr * HCAT + i]);
    __syncthreads();

    float acc = bfc1[t];
#pragma unroll 8
    for (int k = 0; k < HCAT; k++) acc += g[k] * Wfc1[k * 160 + t];
    z[t] = fmaxf(acc, 0.f);
    __syncthreads();

    if (t < 10) {
        float o = bfc2[t];
#pragma unroll 8
        for (int k = 0; k < 160; k++) o += z[k] * Wfc2[k * 10 + t];
        out[gr * 10 + t] = o;
    }
}

// ---------------- launch ----------------

extern "C" void kernel_launch(void* const* d_in, const int* in_sizes, int n_in,
                              void* d_out, int out_size) {
    const float* x     = (const float*)d_in[0];
    const int*   eidx  = (const int*)d_in[1];       // [2, E] row-major
    const int*   batch = (const int*)d_in[2];
    const float* info  = (const float*)d_in[3];
    const float* Wl[3] = { (const float*)d_in[4], (const float*)d_in[7],  (const float*)d_in[10] };
    const float* Wr[3] = { (const float*)d_in[5], (const float*)d_in[8],  (const float*)d_in[11] };
    const float* bb[3] = { (const float*)d_in[6], (const float*)d_in[9],  (const float*)d_in[12] };
    const float* Wfc1  = (const float*)d_in[13];
    const float* bfc1  = (const float*)d_in[14];
    const float* Wfc2  = (const float*)d_in[15];
    const float* bfc2  = (const float*)d_in[16];
    float* out = (float*)d_out;

    const int* src = eidx;
    const int* dst = eidx + N_EDGES;

    const int T = 256;

    // CSR build + pool-max init (edges constant across layers -> build once)
    init_kernel<<<(NUM_GRAPHS * HCAT + T - 1) / T, T>>>();
    deg_kernel<<<(N_EDGES + T - 1) / T, T>>>(dst);
    scan_kernel<<<1, 1024>>>();
    fill_kernel<<<(N_EDGES + T - 1) / T, T>>>(src, dst);

    float* hptr = nullptr;
    cudaGetSymbolAddress((void**)&hptr, d_h);

    int dh_arr[3]  = { 96, 128, 128 };
    int din_arr[3] = { 128, 160, 160 };

    for (int layer = 0; layer < 3; layer++) {
        int dh = dh_arr[layer], din = din_arr[layer];
        const float* hsrc = (layer == 0) ? x : hptr;

        pack_w<<<(din * 128 + T - 1) / T, T>>>(Wl[layer], Wr[layer], din);

        gemm_kernel<<<dim3((N_NODES + 63) / 64, 4), 256>>>(hsrc, dh, info, batch, din);

        gather_combine<<<(N_NODES * 32 + T - 1) / T, T>>>(bb[layer], batch, layer);
    }

    fc_kernel<<<NUM_GRAPHS, 160>>>(Wfc1, bfc1, Wfc2, bfc2, out);
    (void)in_sizes; (void)n_in; (void)out_size;
}

// round 5
// speedup vs baseline: 1.9700x; 1.0723x over previous
#include <cuda_runtime.h>
#include <cuda_bf16.h>
#include <cstdint>

#define N_NODES    50000
#define N_EDGES    800000
#define NUM_GRAPHS 500
#define CONV_OUT   128
#define HCAT       384
#define KPAD_MAX   192

// ---------------- scratch (static device globals) ----------------
__device__ float          d_projL[N_NODES * CONV_OUT];
__device__ float          d_projR[N_NODES * CONV_OUT];
__device__ float          d_h[N_NODES * CONV_OUT];
__device__ int            d_count[N_NODES];
__device__ int            d_rowptr[N_NODES + 1];
__device__ int            d_cursor[N_NODES];
__device__ int            d_adj[N_EDGES];
__device__ unsigned       d_genc[NUM_GRAPHS * HCAT];
__device__ __nv_bfloat16  d_Bhi[KPAD_MAX * 256];   // [k][n]
__device__ __nv_bfloat16  d_Blo[KPAD_MAX * 256];   // [k][n]

// monotone float <-> uint encoding for atomicMax on signed floats
__device__ __forceinline__ unsigned encf(float f) {
    unsigned u = __float_as_uint(f);
    return (u & 0x80000000u) ? ~u : (u | 0x80000000u);
}
__device__ __forceinline__ float decf(unsigned u) {
    u = (u & 0x80000000u) ? (u & 0x7FFFFFFFu) : ~u;
    return __uint_as_float(u);
}
#define ENC_NEG_INF 0x007FFFFFu

__device__ __forceinline__ uint32_t smem_u32(const void* p) {
    uint32_t a;
    asm("{ .reg .u64 t; cvta.to.shared.u64 t, %1; cvt.u32.u64 %0, t; }" : "=r"(a) : "l"(p));
    return a;
}

#define LDSM_X4(r, addr) \
    asm volatile("ldmatrix.sync.aligned.m8n8.x4.shared.b16 {%0,%1,%2,%3}, [%4];" \
        : "=r"((r)[0]), "=r"((r)[1]), "=r"((r)[2]), "=r"((r)[3]) : "r"(addr))

#define LDSM_X4_T(r, addr) \
    asm volatile("ldmatrix.sync.aligned.m8n8.x4.trans.shared.b16 {%0,%1,%2,%3}, [%4];" \
        : "=r"((r)[0]), "=r"((r)[1]), "=r"((r)[2]), "=r"((r)[3]) : "r"(addr))

#define MMA_BF16(c, a, b0, b1) \
    asm volatile("mma.sync.aligned.m16n8k16.row.col.f32.bf16.bf16.f32 " \
        "{%0,%1,%2,%3}, {%4,%5,%6,%7}, {%8,%9}, {%0,%1,%2,%3};" \
        : "+f"((c)[0]), "+f"((c)[1]), "+f"((c)[2]), "+f"((c)[3]) \
        : "r"((a)[0]), "r"((a)[1]), "r"((a)[2]), "r"((a)[3]), "r"(b0), "r"(b1))

// ---------------- graph-structure kernels ----------------
__global__ void init_kernel() {
    int i = blockIdx.x * blockDim.x + threadIdx.x;
    if (i < N_NODES) d_count[i] = 0;
    if (i < NUM_GRAPHS * HCAT) d_genc[i] = ENC_NEG_INF;
}

__global__ void deg_kernel(const int* __restrict__ dst) {
    int e = blockIdx.x * blockDim.x + threadIdx.x;
    if (e < N_EDGES) atomicAdd(&d_count[dst[e]], 1);
}

__global__ void scan_kernel() {
    __shared__ int s[1024];
    int t = threadIdx.x;
    const int CH = (N_NODES + 1023) / 1024;
    int base = t * CH;
    int lim = min(base + CH, N_NODES);
    int sum = 0;
    for (int i = base; i < lim; i++) sum += d_count[i];
    s[t] = sum;
    __syncthreads();
    for (int off = 1; off < 1024; off <<= 1) {
        int v = (t >= off) ? s[t - off] : 0;
        __syncthreads();
        s[t] += v;
        __syncthreads();
    }
    int run = s[t] - sum;
    for (int i = base; i < lim; i++) {
        d_rowptr[i] = run;
        d_cursor[i] = run;
        run += d_count[i];
    }
    if (t == 1023) d_rowptr[N_NODES] = s[1023];
}

__global__ void fill_kernel(const int* __restrict__ src, const int* __restrict__ dst) {
    int e = blockIdx.x * blockDim.x + threadIdx.x;
    if (e < N_EDGES) {
        int pos = atomicAdd(&d_cursor[dst[e]], 1);
        d_adj[pos] = src[e];
    }
}

// B[k][n]: n<128 -> Wl col n, n>=128 -> Wr col n-128; split bf16 hi/lo
__global__ void pack_w(const float* __restrict__ Wl, const float* __restrict__ Wr,
                       int K, int Kpad) {
    int i = blockIdx.x * blockDim.x + threadIdx.x;
    if (i < Kpad * 256) {
        int k = i >> 8, n = i & 255;
        float v = 0.f;
        if (k < K) v = (n < 128) ? Wl[k * 128 + n] : Wr[k * 128 + (n - 128)];
        __nv_bfloat16 hi = __float2bfloat16(v);
        __nv_bfloat16 lo = __float2bfloat16(v - __bfloat162float(hi));
        d_Bhi[i] = hi;
        d_Blo[i] = lo;
    }
}

// ---------------- split-bf16 mma.sync GEMM ----------------
// C[M,256] = concat(h, info[batch]) @ Wcat; grid.y selects N-half (0->projL, 1->projR)
// CTA: 128x128 tile, 8 warps (4 M x 2 N), warp 32x64, K chunk 64.
// A smem: 128 rows x 64 bf16, pitch 144B. B smem: 64 k x 128 n, pitch 272B.
#define SA_PITCH 144
#define SB_PITCH 272
#define SM_AHI 0
#define SM_ALO 18432
#define SM_BHI 36864
#define SM_BLO 54272
#define SM_TOTAL 71680

__global__ void __launch_bounds__(256)
sage_gemm(const float* __restrict__ hsrc, int dh,
          const float* __restrict__ info, const int* __restrict__ batch,
          int K, int nch) {
    extern __shared__ char smem[];
    uint32_t sb = smem_u32(smem);
    const int M = N_NODES;
    int bm = blockIdx.x * 128;
    int nh = blockIdx.y;             // 0: cols 0..127 (projL), 1: 128..255 (projR)
    int tid = threadIdx.x;
    int wid = tid >> 5;
    int lane = tid & 31;
    int wm = wid & 3, wn = wid >> 2; // warp tile: rows wm*32, cols wn*64
    int g = lane >> 2, t4 = lane & 3;

    __shared__ int sbatch[128];
    if (tid < 128) {
        int row = bm + tid;
        sbatch[tid] = (row < M) ? batch[row] : 0;
    }
    __syncthreads();

    float acc[2][8][4];
#pragma unroll
    for (int mt = 0; mt < 2; mt++)
#pragma unroll
        for (int nt = 0; nt < 8; nt++)
#pragma unroll
            for (int j = 0; j < 4; j++) acc[mt][nt][j] = 0.f;

    const uint32_t* Bhi32 = (const uint32_t*)d_Bhi;
    const uint32_t* Blo32 = (const uint32_t*)d_Blo;

    for (int kc = 0; kc < nch; kc++) {
        int c0 = kc * 64;
        if (kc) __syncthreads();

        // ---- A chunk: 128 rows x 64 cols, fused concat + fp32->bf16 hi/lo split
        for (int idx = tid; idx < 128 * 32; idx += 256) {
            int r = idx >> 5, p = idx & 31;
            int col = c0 + p * 2;
            int row = bm + r;
            float2 v = make_float2(0.f, 0.f);
            if (row < M && col < K) {
                v = (col < dh) ? *(const float2*)&hsrc[(size_t)row * dh + col]
                               : *(const float2*)&info[sbatch[r] * 32 + (col - dh)];
            }
            __nv_bfloat16 h0 = __float2bfloat16(v.x);
            __nv_bfloat16 h1 = __float2bfloat16(v.y);
            __nv_bfloat16 l0 = __float2bfloat16(v.x - __bfloat162float(h0));
            __nv_bfloat16 l1 = __float2bfloat16(v.y - __bfloat162float(h1));
            uint32_t hv = ((uint32_t)__bfloat16_as_ushort(h1) << 16) | __bfloat16_as_ushort(h0);
            uint32_t lv = ((uint32_t)__bfloat16_as_ushort(l1) << 16) | __bfloat16_as_ushort(l0);
            uint32_t off = (uint32_t)(r * SA_PITCH + p * 4);
            *(uint32_t*)(smem + SM_AHI + off) = hv;
            *(uint32_t*)(smem + SM_ALO + off) = lv;
        }

        // ---- B chunk: 64 k-rows x 128 cols (this CTA's N-half), 16B loads
        for (int idx = tid; idx < 64 * 16; idx += 256) {
            int k = idx >> 4, c = idx & 15;
            int gi = (c0 + k) * 32 + nh * 16 + c;       // uint4 index into [k][256]
            uint32_t off = (uint32_t)(k * SB_PITCH + c * 16);
            *(uint4*)(smem + SM_BHI + off) = ((const uint4*)Bhi32)[gi];
            *(uint4*)(smem + SM_BLO + off) = ((const uint4*)Blo32)[gi];
        }
        __syncthreads();

        // ---- 4 k16 steps
#pragma unroll
        for (int kk = 0; kk < 4; kk++) {
            uint32_t ahi[2][4], alo[2][4], bfr[4][4];

            // A fragments (hi & lo) for 2 m-tiles
#pragma unroll
            for (int mt = 0; mt < 2; mt++) {
                uint32_t row = wm * 32 + mt * 16 + (lane & 15);
                uint32_t ab = row * SA_PITCH + ((lane >> 4) << 4) + kk * 32;
                LDSM_X4(ahi[mt], sb + SM_AHI + ab);
                LDSM_X4(alo[mt], sb + SM_ALO + ab);
            }
            // Bhi fragments: 4 x (16k x 16n)
#pragma unroll
            for (int nt2 = 0; nt2 < 4; nt2++) {
                uint32_t kl = kk * 16 + (lane & 15);
                uint32_t bbv = kl * SB_PITCH + ((wn * 64 + nt2 * 16) << 1) + ((lane >> 4) << 4);
                LDSM_X4_T(bfr[nt2], sb + SM_BHI + bbv);
            }
            // terms Ahi*Bhi + Alo*Bhi
#pragma unroll
            for (int mt = 0; mt < 2; mt++)
#pragma unroll
                for (int nt = 0; nt < 8; nt++) {
                    uint32_t b0 = bfr[nt >> 1][(nt & 1) * 2];
                    uint32_t b1 = bfr[nt >> 1][(nt & 1) * 2 + 1];
                    MMA_BF16(acc[mt][nt], ahi[mt], b0, b1);
                    MMA_BF16(acc[mt][nt], alo[mt], b0, b1);
                }
            // Blo fragments (reuse regs)
#pragma unroll
            for (int nt2 = 0; nt2 < 4; nt2++) {
                uint32_t kl = kk * 16 + (lane & 15);
                uint32_t bbv = kl * SB_PITCH + ((wn * 64 + nt2 * 16) << 1) + ((lane >> 4) << 4);
                LDSM_X4_T(bfr[nt2], sb + SM_BLO + bbv);
            }
            // term Ahi*Blo
#pragma unroll
            for (int mt = 0; mt < 2; mt++)
#pragma unroll
                for (int nt = 0; nt < 8; nt++) {
                    uint32_t b0 = bfr[nt >> 1][(nt & 1) * 2];
                    uint32_t b1 = bfr[nt >> 1][(nt & 1) * 2 + 1];
                    MMA_BF16(acc[mt][nt], ahi[mt], b0, b1);
                }
        }
    }

    // ---- epilogue: direct gmem stores (float2 per fragment half)
    float* outp = (nh == 0) ? d_projL : d_projR;
#pragma unroll
    for (int mt = 0; mt < 2; mt++) {
        int r0 = bm + wm * 32 + mt * 16 + g;
#pragma unroll
        for (int nt = 0; nt < 8; nt++) {
            int col = wn * 64 + nt * 8 + t4 * 2;
            if (r0 < M)
                *(float2*)&outp[(size_t)r0 * 128 + col] =
                    make_float2(acc[mt][nt][0], acc[mt][nt][1]);
            if (r0 + 8 < M)
                *(float2*)&outp[(size_t)(r0 + 8) * 128 + col] =
                    make_float2(acc[mt][nt][2], acc[mt][nt][3]);
        }
    }
}

// ---------------- aggregation + pooling ----------------
__global__ void gather_combine(const float* __restrict__ b,
                               const int* __restrict__ batch, int layer) {
    int warp = (blockIdx.x * blockDim.x + threadIdx.x) >> 5;
    int lane = threadIdx.x & 31;
    if (warp >= N_NODES) return;

    int s0 = d_rowptr[warp];
    int s1 = d_rowptr[warp + 1];

    float4 acc = make_float4(0.f, 0.f, 0.f, 0.f);
#pragma unroll 4
    for (int j = s0; j < s1; j++) {
        int nb = d_adj[j];
        float4 v = *(const float4*)&d_projL[(size_t)nb * 128 + lane * 4];
        acc.x += v.x; acc.y += v.y; acc.z += v.z; acc.w += v.w;
    }
    float inv = 1.0f / fmaxf((float)(s1 - s0), 1.0f);
    float4 rr = *(const float4*)&d_projR[(size_t)warp * 128 + lane * 4];
    float4 bb = *(const float4*)&b[lane * 4];
    float4 hv;
    hv.x = acc.x * inv + rr.x + bb.x;
    hv.y = acc.y * inv + rr.y + bb.y;
    hv.z = acc.z * inv + rr.z + bb.z;
    hv.w = acc.w * inv + rr.w + bb.w;
    *(float4*)&d_h[(size_t)warp * 128 + lane * 4] = hv;

    unsigned* gp = &d_genc[batch[warp] * HCAT + layer * 128 + lane * 4];
    atomicMax(gp + 0, encf(hv.x));
    atomicMax(gp + 1, encf(hv.y));
    atomicMax(gp + 2, encf(hv.z));
    atomicMax(gp + 3, encf(hv.w));
}

// ---------------- FC head ----------------
__global__ void fc_kernel(const float* __restrict__ Wfc1, const float* __restrict__ bfc1,
                          const float* __restrict__ Wfc2, const float* __restrict__ bfc2,
                          float* __restrict__ out) {
    __shared__ float g[HCAT];
    __shared__ float z[160];
    int gr = blockIdx.x, t = threadIdx.x;

    for (int i = t; i < HCAT; i += 160) g[i] = decf(d_genc[gr * HCAT + i]);
    __syncthreads();

    float acc = bfc1[t];
#pragma unroll 8
    for (int k = 0; k < HCAT; k++) acc += g[k] * Wfc1[k * 160 + t];
    z[t] = fmaxf(acc, 0.f);
    __syncthreads();

    if (t < 10) {
        float o = bfc2[t];
#pragma unroll 8
        for (int k = 0; k < 160; k++) o += z[k] * Wfc2[k * 10 + t];
        out[gr * 10 + t] = o;
    }
}

// ---------------- launch ----------------
extern "C" void kernel_launch(void* const* d_in, const int* in_sizes, int n_in,
                              void* d_out, int out_size) {
    const float* x     = (const float*)d_in[0];
    const int*   eidx  = (const int*)d_in[1];
    const int*   batch = (const int*)d_in[2];
    const float* info  = (const float*)d_in[3];
    const float* Wl[3] = { (const float*)d_in[4], (const float*)d_in[7],  (const float*)d_in[10] };
    const float* Wr[3] = { (const float*)d_in[5], (const float*)d_in[8],  (const float*)d_in[11] };
    const float* bb[3] = { (const float*)d_in[6], (const float*)d_in[9],  (const float*)d_in[12] };
    const float* Wfc1  = (const float*)d_in[13];
    const float* bfc1  = (const float*)d_in[14];
    const float* Wfc2  = (const float*)d_in[15];
    const float* bfc2  = (const float*)d_in[16];
    float* out = (float*)d_out;

    const int* src = eidx;
    const int* dst = eidx + N_EDGES;
    const int T = 256;

    cudaFuncSetAttribute(sage_gemm, cudaFuncAttributeMaxDynamicSharedMemorySize, SM_TOTAL);

    init_kernel<<<(NUM_GRAPHS * HCAT + T - 1) / T, T>>>();
    deg_kernel<<<(N_EDGES + T - 1) / T, T>>>(dst);
    scan_kernel<<<1, 1024>>>();
    fill_kernel<<<(N_EDGES + T - 1) / T, T>>>(src, dst);

    float* hptr = nullptr;
    cudaGetSymbolAddress((void**)&hptr, d_h);

    int dh_arr[3]   = { 96, 128, 128 };
    int K_arr[3]    = { 128, 160, 160 };
    int Kpad_arr[3] = { 128, 192, 192 };

    for (int layer = 0; layer < 3; layer++) {
        int dh = dh_arr[layer], K = K_arr[layer], Kpad = Kpad_arr[layer];
        int nch = Kpad / 64;
        const float* hsrc = (layer == 0) ? x : hptr;

        pack_w<<<(Kpad * 256 + T - 1) / T, T>>>(Wl[layer], Wr[layer], K, Kpad);

        sage_gemm<<<dim3((N_NODES + 127) / 128, 2), 256, SM_TOTAL>>>(hsrc, dh, info, batch, K, nch);

        gather_combine<<<(N_NODES * 32 + T - 1) / T, T>>>(bb[layer], batch, layer);
    }

    fc_kernel<<<NUM_GRAPHS, 160>>>(Wfc1, bfc1, Wfc2, bfc2, out);
    (void)in_sizes; (void)n_in; (void)out_size;
}

// round 6
// speedup vs baseline: 2.8546x; 1.4490x over previous
#include <cuda_runtime.h>
#include <cuda_bf16.h>
#include <cstdint>

#define N_NODES    50000
#define N_EDGES    800000
#define NUM_GRAPHS 500
#define CONV_OUT   128
#define HCAT       384
#define KPAD_MAX   192
#define STRIDE12   192

// ---------------- scratch (static device globals) ----------------
__device__ float          d_projL[N_NODES * CONV_OUT];
__device__ float          d_projR[N_NODES * CONV_OUT];
__device__ int            d_count[N_NODES];
__device__ int            d_rowptr[N_NODES + 1];
__device__ int            d_cursor[N_NODES];
__device__ int            d_adj[N_EDGES];
__device__ unsigned       d_genc[NUM_GRAPHS * HCAT];
__device__ __nv_bfloat16  d_Bhi[256 * KPAD_MAX];            // [n][k]
__device__ __nv_bfloat16  d_Blo[256 * KPAD_MAX];            // [n][k]
__device__ __nv_bfloat16  d_A0hi[N_NODES * 128];            // layer0 A, [node][128]
__device__ __nv_bfloat16  d_A0lo[N_NODES * 128];
__device__ __nv_bfloat16  d_A12hi[N_NODES * STRIDE12];      // layers1-2 A, [node][192]
__device__ __nv_bfloat16  d_A12lo[N_NODES * STRIDE12];

// monotone float <-> uint encoding for atomicMax on signed floats
__device__ __forceinline__ unsigned encf(float f) {
    unsigned u = __float_as_uint(f);
    return (u & 0x80000000u) ? ~u : (u | 0x80000000u);
}
__device__ __forceinline__ float decf(unsigned u) {
    u = (u & 0x80000000u) ? (u & 0x7FFFFFFFu) : ~u;
    return __uint_as_float(u);
}
#define ENC_NEG_INF 0x007FFFFFu

__device__ __forceinline__ uint32_t smem_u32(const void* p) {
    uint32_t a;
    asm("{ .reg .u64 t; cvta.to.shared.u64 t, %1; cvt.u32.u64 %0, t; }" : "=r"(a) : "l"(p));
    return a;
}

#define LDSM_X4(r, addr) \
    asm volatile("ldmatrix.sync.aligned.m8n8.x4.shared.b16 {%0,%1,%2,%3}, [%4];" \
        : "=r"((r)[0]), "=r"((r)[1]), "=r"((r)[2]), "=r"((r)[3]) : "r"(addr))

#define MMA_BF16(c, a, b0, b1) \
    asm volatile("mma.sync.aligned.m16n8k16.row.col.f32.bf16.bf16.f32 " \
        "{%0,%1,%2,%3}, {%4,%5,%6,%7}, {%8,%9}, {%0,%1,%2,%3};" \
        : "+f"((c)[0]), "+f"((c)[1]), "+f"((c)[2]), "+f"((c)[3]) \
        : "r"((a)[0]), "r"((a)[1]), "r"((a)[2]), "r"((a)[3]), "r"(b0), "r"(b1))

__device__ __forceinline__ void split_bf16(float v, __nv_bfloat16& hi, __nv_bfloat16& lo) {
    hi = __float2bfloat16(v);
    lo = __float2bfloat16(v - __bfloat162float(hi));
}

// ---------------- graph-structure kernels ----------------
__global__ void init_kernel() {
    int i = blockIdx.x * blockDim.x + threadIdx.x;
    if (i < N_NODES) d_count[i] = 0;
    if (i < NUM_GRAPHS * HCAT) d_genc[i] = ENC_NEG_INF;
}

__global__ void deg_kernel(const int* __restrict__ dst) {
    int e = blockIdx.x * blockDim.x + threadIdx.x;
    if (e < N_EDGES) atomicAdd(&d_count[dst[e]], 1);
}

__global__ void scan_kernel() {
    __shared__ int s[1024];
    int t = threadIdx.x;
    const int CH = (N_NODES + 1023) / 1024;
    int base = t * CH;
    int lim = min(base + CH, N_NODES);
    int sum = 0;
    for (int i = base; i < lim; i++) sum += d_count[i];
    s[t] = sum;
    __syncthreads();
    for (int off = 1; off < 1024; off <<= 1) {
        int v = (t >= off) ? s[t - off] : 0;
        __syncthreads();
        s[t] += v;
        __syncthreads();
    }
    int run = s[t] - sum;
    for (int i = base; i < lim; i++) {
        d_rowptr[i] = run;
        d_cursor[i] = run;
        run += d_count[i];
    }
    if (t == 1023) d_rowptr[N_NODES] = s[1023];
}

__global__ void fill_kernel(const int* __restrict__ src, const int* __restrict__ dst) {
    int e = blockIdx.x * blockDim.x + threadIdx.x;
    if (e < N_EDGES) {
        int pos = atomicAdd(&d_cursor[dst[e]], 1);
        d_adj[pos] = src[e];
    }
}

// ---------------- prep kernels ----------------
// layer0 A: [x(96) | info[batch](32)] -> split bf16 [node][128]
__global__ void prep0(const float* __restrict__ x, const float* __restrict__ info,
                      const int* __restrict__ batch) {
    int i = blockIdx.x * blockDim.x + threadIdx.x;
    if (i < N_NODES * 128) {
        int r = i >> 7, c = i & 127;
        float v = (c < 96) ? x[r * 96 + c] : info[batch[r] * 32 + (c - 96)];
        __nv_bfloat16 hi, lo;
        split_bf16(v, hi, lo);
        d_A0hi[i] = hi;
        d_A0lo[i] = lo;
    }
}

// layers1-2 A, static part: cols 128..159 = info[batch], 160..191 = 0 (written once)
__global__ void prepinfo(const float* __restrict__ info, const int* __restrict__ batch) {
    int i = blockIdx.x * blockDim.x + threadIdx.x;
    if (i < N_NODES * 64) {
        int r = i >> 6, c = i & 63;
        float v = (c < 32) ? info[batch[r] * 32 + c] : 0.f;
        __nv_bfloat16 hi, lo;
        split_bf16(v, hi, lo);
        d_A12hi[r * STRIDE12 + 128 + c] = hi;
        d_A12lo[r * STRIDE12 + 128 + c] = lo;
    }
}

// B[n][k]: n<128 -> Wl col n, n>=128 -> Wr col n-128; split bf16 hi/lo, zero-pad k>=K
__global__ void pack_w(const float* __restrict__ Wl, const float* __restrict__ Wr,
                       int K, int Kpad) {
    int i = blockIdx.x * blockDim.x + threadIdx.x;
    if (i < 256 * Kpad) {
        int n = i / Kpad, k = i - n * Kpad;
        float v = 0.f;
        if (k < K) v = (n < 128) ? Wl[k * 128 + n] : Wr[k * 128 + (n - 128)];
        __nv_bfloat16 hi, lo;
        split_bf16(v, hi, lo);
        d_Bhi[i] = hi;
        d_Blo[i] = lo;
    }
}

// ---------------- split-bf16 mma.sync GEMM ----------------
// C[M,256] = A @ Wcat; grid.y selects N-half (0->projL, 1->projR)
// CTA: 128x128 tile, 8 warps (4 M x 2 N), warp 32x64, K chunk 64.
// A smem: 128 rows x 64 bf16, pitch 144B. B smem: 128 n-rows x 64 k bf16, pitch 144B.
#define SP 144
#define SM_AHI 0
#define SM_ALO 18432
#define SM_BHI 36864
#define SM_BLO 55296
#define SM_TOTAL 73728

__global__ void __launch_bounds__(256, 2)
sage_gemm(const __nv_bfloat16* __restrict__ Ahi, const __nv_bfloat16* __restrict__ Alo,
          int strideA, int nch, int Kpad) {
    extern __shared__ char smem[];
    uint32_t sb = smem_u32(smem);
    const int M = N_NODES;
    int bm = blockIdx.x * 128;
    int nh = blockIdx.y;
    int tid = threadIdx.x;
    int wid = tid >> 5;
    int lane = tid & 31;
    int wm = wid & 3, wn = wid >> 2;
    int g = lane >> 2, t4 = lane & 3;

    float acc[2][8][4];
#pragma unroll
    for (int mt = 0; mt < 2; mt++)
#pragma unroll
        for (int nt = 0; nt < 8; nt++)
#pragma unroll
            for (int j = 0; j < 4; j++) acc[mt][nt][j] = 0.f;

    const char* Bhg = (const char*)d_Bhi;
    const char* Blg = (const char*)d_Blo;
    const char* Ahg = (const char*)Ahi;
    const char* Alg = (const char*)Alo;

    for (int kc = 0; kc < nch; kc++) {
        int c0 = kc * 64;
        if (kc) __syncthreads();

        // A chunk: 128 rows x 64 bf16, pure uint4 copies
        const uint4 z4 = make_uint4(0, 0, 0, 0);
#pragma unroll
        for (int it = 0; it < 4; it++) {
            int idx = tid + it * 256;
            int r = idx >> 3, seg = idx & 7;
            int row = bm + r;
            uint4 vh = z4, vl = z4;
            if (row < M) {
                size_t off = ((size_t)row * strideA + c0) * 2 + seg * 16;
                vh = *(const uint4*)(Ahg + off);
                vl = *(const uint4*)(Alg + off);
            }
            uint32_t so = (uint32_t)(r * SP + seg * 16);
            *(uint4*)(smem + SM_AHI + so) = vh;
            *(uint4*)(smem + SM_ALO + so) = vl;
        }
        // B chunk: 128 n-rows x 64 k bf16
#pragma unroll
        for (int it = 0; it < 4; it++) {
            int idx = tid + it * 256;
            int n = idx >> 3, seg = idx & 7;
            size_t off = ((size_t)(nh * 128 + n) * Kpad + c0) * 2 + seg * 16;
            uint32_t so = (uint32_t)(n * SP + seg * 16);
            *(uint4*)(smem + SM_BHI + so) = *(const uint4*)(Bhg + off);
            *(uint4*)(smem + SM_BLO + so) = *(const uint4*)(Blg + off);
        }
        __syncthreads();

#pragma unroll
        for (int kk = 0; kk < 4; kk++) {
            uint32_t ahi[2][4], alo[2][4], bfr[4][4];

#pragma unroll
            for (int mt = 0; mt < 2; mt++) {
                uint32_t ab = (uint32_t)((wm * 32 + mt * 16 + (lane & 15)) * SP
                               + ((lane >> 4) << 4) + kk * 32);
                LDSM_X4(ahi[mt], sb + SM_AHI + ab);
                LDSM_X4(alo[mt], sb + SM_ALO + ab);
            }
            // B frags from [n][k] layout, non-trans ldmatrix
            uint32_t brow = (lane & 7) + ((lane >> 4) << 3);
            uint32_t bkof = ((lane >> 3) & 1) << 4;
#pragma unroll
            for (int nt2 = 0; nt2 < 4; nt2++) {
                uint32_t bb = (uint32_t)((wn * 64 + nt2 * 16 + brow) * SP + kk * 32 + bkof);
                LDSM_X4(bfr[nt2], sb + SM_BHI + bb);
            }
#pragma unroll
            for (int mt = 0; mt < 2; mt++)
#pragma unroll
                for (int nt = 0; nt < 8; nt++) {
                    uint32_t b0 = bfr[nt >> 1][(nt & 1) * 2];
                    uint32_t b1 = bfr[nt >> 1][(nt & 1) * 2 + 1];
                    MMA_BF16(acc[mt][nt], ahi[mt], b0, b1);
                    MMA_BF16(acc[mt][nt], alo[mt], b0, b1);
                }
#pragma unroll
            for (int nt2 = 0; nt2 < 4; nt2++) {
                uint32_t bb = (uint32_t)((wn * 64 + nt2 * 16 + brow) * SP + kk * 32 + bkof);
                LDSM_X4(bfr[nt2], sb + SM_BLO + bb);
            }
#pragma unroll
            for (int mt = 0; mt < 2; mt++)
#pragma unroll
                for (int nt = 0; nt < 8; nt++) {
                    uint32_t b0 = bfr[nt >> 1][(nt & 1) * 2];
                    uint32_t b1 = bfr[nt >> 1][(nt & 1) * 2 + 1];
                    MMA_BF16(acc[mt][nt], ahi[mt], b0, b1);
                }
        }
    }

    float* outp = (nh == 0) ? d_projL : d_projR;
#pragma unroll
    for (int mt = 0; mt < 2; mt++) {
        int r0 = bm + wm * 32 + mt * 16 + g;
#pragma unroll
        for (int nt = 0; nt < 8; nt++) {
            int col = wn * 64 + nt * 8 + t4 * 2;
            if (r0 < M)
                *(float2*)&outp[(size_t)r0 * 128 + col] =
                    make_float2(acc[mt][nt][0], acc[mt][nt][1]);
            if (r0 + 8 < M)
                *(float2*)&outp[(size_t)(r0 + 8) * 128 + col] =
                    make_float2(acc[mt][nt][2], acc[mt][nt][3]);
        }
    }
}

// ---------------- aggregation + pooling (+ next-layer A write) ----------------
__global__ void gather_combine(const float* __restrict__ b,
                               const int* __restrict__ batch, int layer, int write_a) {
    int warp = (blockIdx.x * blockDim.x + threadIdx.x) >> 5;
    int lane = threadIdx.x & 31;
    if (warp >= N_NODES) return;

    int s0 = d_rowptr[warp];
    int s1 = d_rowptr[warp + 1];

    float4 acc = make_float4(0.f, 0.f, 0.f, 0.f);
#pragma unroll 4
    for (int j = s0; j < s1; j++) {
        int nb = d_adj[j];
        float4 v = *(const float4*)&d_projL[(size_t)nb * 128 + lane * 4];
        acc.x += v.x; acc.y += v.y; acc.z += v.z; acc.w += v.w;
    }
    float inv = 1.0f / fmaxf((float)(s1 - s0), 1.0f);
    float4 rr = *(const float4*)&d_projR[(size_t)warp * 128 + lane * 4];
    float4 bb = *(const float4*)&b[lane * 4];
    float hv[4];
    hv[0] = acc.x * inv + rr.x + bb.x;
    hv[1] = acc.y * inv + rr.y + bb.y;
    hv[2] = acc.z * inv + rr.z + bb.z;
    hv[3] = acc.w * inv + rr.w + bb.w;

    if (write_a) {
        uint32_t hp[2], lp[2];
#pragma unroll
        for (int p = 0; p < 2; p++) {
            __nv_bfloat16 h0, l0, h1, l1;
            split_bf16(hv[p * 2], h0, l0);
            split_bf16(hv[p * 2 + 1], h1, l1);
            hp[p] = ((uint32_t)__bfloat16_as_ushort(h1) << 16) | __bfloat16_as_ushort(h0);
            lp[p] = ((uint32_t)__bfloat16_as_ushort(l1) << 16) | __bfloat16_as_ushort(l0);
        }
        size_t off = (size_t)warp * STRIDE12 + lane * 4;
        *(uint2*)&d_A12hi[off] = make_uint2(hp[0], hp[1]);
        *(uint2*)&d_A12lo[off] = make_uint2(lp[0], lp[1]);
    }

    unsigned* gp = &d_genc[batch[warp] * HCAT + layer * 128 + lane * 4];
    atomicMax(gp + 0, encf(hv[0]));
    atomicMax(gp + 1, encf(hv[1]));
    atomicMax(gp + 2, encf(hv[2]));
    atomicMax(gp + 3, encf(hv[3]));
}

// ---------------- FC head ----------------
__global__ void fc_kernel(const float* __restrict__ Wfc1, const float* __restrict__ bfc1,
                          const float* __restrict__ Wfc2, const float* __restrict__ bfc2,
                          float* __restrict__ out) {
    __shared__ float g[HCAT];
    __shared__ float z[160];
    int gr = blockIdx.x, t = threadIdx.x;

    for (int i = t; i < HCAT; i += 160) g[i] = decf(d_genc[gr * HCAT + i]);
    __syncthreads();

    float acc = bfc1[t];
#pragma unroll 8
    for (int k = 0; k < HCAT; k++) acc += g[k] * Wfc1[k * 160 + t];
    z[t] = fmaxf(acc, 0.f);
    __syncthreads();

    if (t < 10) {
        float o = bfc2[t];
#pragma unroll 8
        for (int k = 0; k < 160; k++) o += z[k] * Wfc2[k * 10 + t];
        out[gr * 10 + t] = o;
    }
}

// ---------------- launch ----------------
extern "C" void kernel_launch(void* const* d_in, const int* in_sizes, int n_in,
                              void* d_out, int out_size) {
    const float* x     = (const float*)d_in[0];
    const int*   eidx  = (const int*)d_in[1];
    const int*   batch = (const int*)d_in[2];
    const float* info  = (const float*)d_in[3];
    const float* Wl[3] = { (const float*)d_in[4], (const float*)d_in[7],  (const float*)d_in[10] };
    const float* Wr[3] = { (const float*)d_in[5], (const float*)d_in[8],  (const float*)d_in[11] };
    const float* bb[3] = { (const float*)d_in[6], (const float*)d_in[9],  (const float*)d_in[12] };
    const float* Wfc1  = (const float*)d_in[13];
    const float* bfc1  = (const float*)d_in[14];
    const float* Wfc2  = (const float*)d_in[15];
    const float* bfc2  = (const float*)d_in[16];
    float* out = (float*)d_out;

    const int* src = eidx;
    const int* dst = eidx + N_EDGES;
    const int T = 256;

    cudaFuncSetAttribute(sage_gemm, cudaFuncAttributeMaxDynamicSharedMemorySize, SM_TOTAL);

    init_kernel<<<(NUM_GRAPHS * HCAT + T - 1) / T, T>>>();
    deg_kernel<<<(N_EDGES + T - 1) / T, T>>>(dst);
    scan_kernel<<<1, 1024>>>();
    fill_kernel<<<(N_EDGES + T - 1) / T, T>>>(src, dst);
    prep0<<<(N_NODES * 128 + T - 1) / T, T>>>(x, info, batch);
    prepinfo<<<(N_NODES * 64 + T - 1) / T, T>>>(info, batch);

    __nv_bfloat16 *a0h = nullptr, *a0l = nullptr, *a12h = nullptr, *a12l = nullptr;
    cudaGetSymbolAddress((void**)&a0h, d_A0hi);
    cudaGetSymbolAddress((void**)&a0l, d_A0lo);
    cudaGetSymbolAddress((void**)&a12h, d_A12hi);
    cudaGetSymbolAddress((void**)&a12l, d_A12lo);

    int K_arr[3]    = { 128, 160, 160 };
    int Kpad_arr[3] = { 128, 192, 192 };

    for (int layer = 0; layer < 3; layer++) {
        int K = K_arr[layer], Kpad = Kpad_arr[layer];
        int nch = Kpad / 64;
        const __nv_bfloat16* Ah = (layer == 0) ? a0h : a12h;
        const __nv_bfloat16* Al = (layer == 0) ? a0l : a12l;
        int strideA = (layer == 0) ? 128 : STRIDE12;

        pack_w<<<(256 * Kpad + T - 1) / T, T>>>(Wl[layer], Wr[layer], K, Kpad);

        sage_gemm<<<dim3((N_NODES + 127) / 128, 2), 256, SM_TOTAL>>>(Ah, Al, strideA, nch, Kpad);

        gather_combine<<<(N_NODES * 32 + T - 1) / T, T>>>(bb[layer], batch, layer, layer < 2);
    }

    fc_kernel<<<NUM_GRAPHS, 160>>>(Wfc1, bfc1, Wfc2, bfc2, out);
    (void)in_sizes; (void)n_in; (void)out_size;
}

// round 7
// speedup vs baseline: 2.9551x; 1.0352x over previous
#include <cuda_runtime.h>
#include <cuda_bf16.h>
#include <cstdint>

#define N_NODES    50000
#define N_EDGES    800000
#define NUM_GRAPHS 500
#define CONV_OUT   128
#define HCAT       384
#define KPAD       192
#define STRIDE12   192

// ---------------- scratch (static device globals) ----------------
__device__ float          d_projL[N_NODES * CONV_OUT];
__device__ float          d_projR[N_NODES * CONV_OUT];
__device__ int            d_count[N_NODES];
__device__ int            d_rowptr[N_NODES + 1];
__device__ int            d_cursor[N_NODES];
__device__ int            d_adj[N_EDGES];
__device__ unsigned       d_genc[NUM_GRAPHS * HCAT];
__device__ __nv_bfloat16  d_Bhi[3 * 256 * KPAD];            // [layer][n][k]
__device__ __nv_bfloat16  d_Blo[3 * 256 * KPAD];
__device__ __nv_bfloat16  d_A0hi[N_NODES * 128];            // layer0 A, [node][128]
__device__ __nv_bfloat16  d_A0lo[N_NODES * 128];
__device__ __nv_bfloat16  d_A12hi[N_NODES * STRIDE12];      // layers1-2 A, [node][192]
__device__ __nv_bfloat16  d_A12lo[N_NODES * STRIDE12];

// monotone float <-> uint encoding for atomicMax on signed floats
__device__ __forceinline__ unsigned encf(float f) {
    unsigned u = __float_as_uint(f);
    return (u & 0x80000000u) ? ~u : (u | 0x80000000u);
}
__device__ __forceinline__ float decf(unsigned u) {
    u = (u & 0x80000000u) ? (u & 0x7FFFFFFFu) : ~u;
    return __uint_as_float(u);
}
#define ENC_NEG_INF 0x007FFFFFu

__device__ __forceinline__ uint32_t smem_u32(const void* p) {
    uint32_t a;
    asm("{ .reg .u64 t; cvta.to.shared.u64 t, %1; cvt.u32.u64 %0, t; }" : "=r"(a) : "l"(p));
    return a;
}

__device__ __forceinline__ void cp16(uint32_t dst, const void* src, bool pred) {
    int sz = pred ? 16 : 0;
    asm volatile("cp.async.cg.shared.global [%0], [%1], 16, %2;"
                 :: "r"(dst), "l"(src), "r"(sz) : "memory");
}
#define CP_COMMIT()  asm volatile("cp.async.commit_group;" ::: "memory")
#define CP_WAIT(n)   asm volatile("cp.async.wait_group %0;" :: "n"(n) : "memory")

#define LDSM_X4(r, addr) \
    asm volatile("ldmatrix.sync.aligned.m8n8.x4.shared.b16 {%0,%1,%2,%3}, [%4];" \
        : "=r"((r)[0]), "=r"((r)[1]), "=r"((r)[2]), "=r"((r)[3]) : "r"(addr))

#define MMA_BF16(c, a, b0, b1) \
    asm volatile("mma.sync.aligned.m16n8k16.row.col.f32.bf16.bf16.f32 " \
        "{%0,%1,%2,%3}, {%4,%5,%6,%7}, {%8,%9}, {%0,%1,%2,%3};" \
        : "+f"((c)[0]), "+f"((c)[1]), "+f"((c)[2]), "+f"((c)[3]) \
        : "r"((a)[0]), "r"((a)[1]), "r"((a)[2]), "r"((a)[3]), "r"(b0), "r"(b1))

__device__ __forceinline__ void split_bf16(float v, __nv_bfloat16& hi, __nv_bfloat16& lo) {
    hi = __float2bfloat16(v);
    lo = __float2bfloat16(v - __bfloat162float(hi));
}

// ---------------- graph-structure kernels ----------------
__global__ void init_kernel() {
    int i = blockIdx.x * blockDim.x + threadIdx.x;
    if (i < N_NODES) d_count[i] = 0;
    if (i < NUM_GRAPHS * HCAT) d_genc[i] = ENC_NEG_INF;
}

__global__ void deg_kernel(const int* __restrict__ dst) {
    int e = blockIdx.x * blockDim.x + threadIdx.x;
    if (e < N_EDGES) atomicAdd(&d_count[dst[e]], 1);
}

__global__ void scan_kernel() {
    __shared__ int s[1024];
    int t = threadIdx.x;
    const int CH = (N_NODES + 1023) / 1024;
    int base = t * CH;
    int lim = min(base + CH, N_NODES);
    int sum = 0;
    for (int i = base; i < lim; i++) sum += d_count[i];
    s[t] = sum;
    __syncthreads();
    for (int off = 1; off < 1024; off <<= 1) {
        int v = (t >= off) ? s[t - off] : 0;
        __syncthreads();
        s[t] += v;
        __syncthreads();
    }
    int run = s[t] - sum;
    for (int i = base; i < lim; i++) {
        d_rowptr[i] = run;
        d_cursor[i] = run;
        run += d_count[i];
    }
    if (t == 1023) d_rowptr[N_NODES] = s[1023];
}

__global__ void fill_kernel(const int* __restrict__ src, const int* __restrict__ dst) {
    int e = blockIdx.x * blockDim.x + threadIdx.x;
    if (e < N_EDGES) {
        int pos = atomicAdd(&d_cursor[dst[e]], 1);
        d_adj[pos] = src[e];
    }
}

// ---------------- prep kernels ----------------
// layer0 A: [x(96) | info[batch](32)] -> split bf16 [node][128]
__global__ void prep0(const float* __restrict__ x, const float* __restrict__ info,
                      const int* __restrict__ batch) {
    int i = blockIdx.x * blockDim.x + threadIdx.x;
    if (i < N_NODES * 128) {
        int r = i >> 7, c = i & 127;
        float v = (c < 96) ? x[r * 96 + c] : info[batch[r] * 32 + (c - 96)];
        __nv_bfloat16 hi, lo;
        split_bf16(v, hi, lo);
        d_A0hi[i] = hi;
        d_A0lo[i] = lo;
    }
}

// layers1-2 A, static part: cols 128..159 = info[batch] (written once)
__global__ void prepinfo(const float* __restrict__ info, const int* __restrict__ batch) {
    int i = blockIdx.x * blockDim.x + threadIdx.x;
    if (i < N_NODES * 32) {
        int r = i >> 5, c = i & 31;
        float v = info[batch[r] * 32 + c];
        __nv_bfloat16 hi, lo;
        split_bf16(v, hi, lo);
        d_A12hi[r * STRIDE12 + 128 + c] = hi;
        d_A12lo[r * STRIDE12 + 128 + c] = lo;
    }
}

// all 3 layers' B[n][k]: n<128 -> Wl col n, n>=128 -> Wr col n-128; split bf16
__global__ void pack_all(const float* __restrict__ Wl0, const float* __restrict__ Wr0,
                         const float* __restrict__ Wl1, const float* __restrict__ Wr1,
                         const float* __restrict__ Wl2, const float* __restrict__ Wr2) {
    int i = blockIdx.x * blockDim.x + threadIdx.x;
    if (i >= 3 * 256 * KPAD) return;
    int layer = i / (256 * KPAD);
    int rem = i - layer * (256 * KPAD);
    int n = rem / KPAD, k = rem - n * KPAD;
    int K = (layer == 0) ? 128 : 160;
    const float* Wl = (layer == 0) ? Wl0 : (layer == 1) ? Wl1 : Wl2;
    const float* Wr = (layer == 0) ? Wr0 : (layer == 1) ? Wr1 : Wr2;
    float v = 0.f;
    if (k < K) v = (n < 128) ? Wl[k * 128 + n] : Wr[k * 128 + (n - 128)];
    __nv_bfloat16 hi, lo;
    split_bf16(v, hi, lo);
    d_Bhi[i] = hi;
    d_Blo[i] = lo;
}

// ---------------- split-bf16 mma.sync GEMM, cp.async 2-stage pipeline ----------------
// C[M,256] = A @ Wcat; grid.y selects N-half (0->projL, 1->projR)
// CTA: 128x128 tile, 8 warps (4M x 2N), warp 32x64. K chunk 32, 2 stages.
#define PITCH 80
#define ABUF  10240              // 128 * 80
#define ST_AHI 0
#define ST_ALO 10240
#define ST_BHI 20480
#define ST_BLO 30720
#define STAGE  40960
#define SM_TOTAL 81920

__global__ void __launch_bounds__(256, 2)
sage_gemm(const __nv_bfloat16* __restrict__ Ahi, const __nv_bfloat16* __restrict__ Alo,
          const __nv_bfloat16* __restrict__ Bhi, const __nv_bfloat16* __restrict__ Blo,
          int strideA, int nch) {
    extern __shared__ char smem[];
    uint32_t sb = smem_u32(smem);
    const int M = N_NODES;
    int bm = blockIdx.x * 128;
    int nh = blockIdx.y;
    int tid = threadIdx.x;
    int wid = tid >> 5;
    int lane = tid & 31;
    int wm = wid & 3, wn = wid >> 2;
    int g = lane >> 2, t4 = lane & 3;

    const char* Ahg = (const char*)Ahi;
    const char* Alg = (const char*)Alo;
    const char* Bhg = (const char*)Bhi;
    const char* Blg = (const char*)Blo;

    // per-thread load coordinates: 512 (row,seg) pairs over 256 threads -> 2 iters
    int r0i = tid >> 2, seg0 = tid & 3;            // iter 0
    int r1i = (tid + 256) >> 2, seg1 = tid & 3;    // iter 1 (seg same: (tid+256)&3 == tid&3)
    bool p0 = (bm + r0i) < M;
    bool p1 = (bm + r1i) < M;

    float acc[2][8][4];
#pragma unroll
    for (int mt = 0; mt < 2; mt++)
#pragma unroll
        for (int nt = 0; nt < 8; nt++)
#pragma unroll
            for (int j = 0; j < 4; j++) acc[mt][nt][j] = 0.f;

    // ---- load chunk kc into stage s
    auto load_chunk = [&](int s, int kc) {
        int c0 = kc * 32;
        uint32_t st = sb + s * STAGE;
        size_t aoff0 = ((size_t)(bm + r0i) * strideA + c0) * 2 + seg0 * 16;
        size_t aoff1 = ((size_t)(bm + r1i) * strideA + c0) * 2 + seg1 * 16;
        uint32_t so0 = r0i * PITCH + seg0 * 16;
        uint32_t so1 = r1i * PITCH + seg1 * 16;
        cp16(st + ST_AHI + so0, Ahg + aoff0, p0);
        cp16(st + ST_AHI + so1, Ahg + aoff1, p1);
        cp16(st + ST_ALO + so0, Alg + aoff0, p0);
        cp16(st + ST_ALO + so1, Alg + aoff1, p1);
        size_t boff0 = ((size_t)(nh * 128 + r0i) * KPAD + c0) * 2 + seg0 * 16;
        size_t boff1 = ((size_t)(nh * 128 + r1i) * KPAD + c0) * 2 + seg1 * 16;
        cp16(st + ST_BHI + so0, Bhg + boff0, true);
        cp16(st + ST_BHI + so1, Bhg + boff1, true);
        cp16(st + ST_BLO + so0, Blg + boff0, true);
        cp16(st + ST_BLO + so1, Blg + boff1, true);
    };

    load_chunk(0, 0);
    CP_COMMIT();

    uint32_t brow = (lane & 7) + ((lane >> 4) << 3);
    uint32_t bkof = ((lane >> 3) & 1) << 4;

    for (int kc = 0; kc < nch; kc++) {
        if (kc + 1 < nch) {
            load_chunk((kc + 1) & 1, kc + 1);
            CP_COMMIT();
            CP_WAIT(1);
        } else {
            CP_WAIT(0);
        }
        __syncthreads();

        uint32_t st = sb + (kc & 1) * STAGE;
#pragma unroll
        for (int kk = 0; kk < 2; kk++) {
            uint32_t ahi[2][4], alo[2][4], bfr[4][4];
#pragma unroll
            for (int mt = 0; mt < 2; mt++) {
                uint32_t ab = (uint32_t)((wm * 32 + mt * 16 + (lane & 15)) * PITCH
                               + kk * 32 + ((lane >> 4) << 4));
                LDSM_X4(ahi[mt], st + ST_AHI + ab);
                LDSM_X4(alo[mt], st + ST_ALO + ab);
            }
#pragma unroll
            for (int nt2 = 0; nt2 < 4; nt2++) {
                uint32_t bb = (uint32_t)((wn * 64 + nt2 * 16 + brow) * PITCH + kk * 32 + bkof);
                LDSM_X4(bfr[nt2], st + ST_BHI + bb);
            }
#pragma unroll
            for (int mt = 0; mt < 2; mt++)
#pragma unroll
                for (int nt = 0; nt < 8; nt++) {
                    uint32_t b0 = bfr[nt >> 1][(nt & 1) * 2];
                    uint32_t b1 = bfr[nt >> 1][(nt & 1) * 2 + 1];
                    MMA_BF16(acc[mt][nt], ahi[mt], b0, b1);
                    MMA_BF16(acc[mt][nt], alo[mt], b0, b1);
                }
#pragma unroll
            for (int nt2 = 0; nt2 < 4; nt2++) {
                uint32_t bb = (uint32_t)((wn * 64 + nt2 * 16 + brow) * PITCH + kk * 32 + bkof);
                LDSM_X4(bfr[nt2], st + ST_BLO + bb);
            }
#pragma unroll
            for (int mt = 0; mt < 2; mt++)
#pragma unroll
                for (int nt = 0; nt < 8; nt++) {
                    uint32_t b0 = bfr[nt >> 1][(nt & 1) * 2];
                    uint32_t b1 = bfr[nt >> 1][(nt & 1) * 2 + 1];
                    MMA_BF16(acc[mt][nt], ahi[mt], b0, b1);
                }
        }
        __syncthreads();
    }

    float* outp = (nh == 0) ? d_projL : d_projR;
#pragma unroll
    for (int mt = 0; mt < 2; mt++) {
        int r0 = bm + wm * 32 + mt * 16 + g;
#pragma unroll
        for (int nt = 0; nt < 8; nt++) {
            int col = wn * 64 + nt * 8 + t4 * 2;
            if (r0 < M)
                *(float2*)&outp[(size_t)r0 * 128 + col] =
                    make_float2(acc[mt][nt][0], acc[mt][nt][1]);
            if (r0 + 8 < M)
                *(float2*)&outp[(size_t)(r0 + 8) * 128 + col] =
                    make_float2(acc[mt][nt][2], acc[mt][nt][3]);
        }
    }
}

// ---------------- aggregation + pooling (+ next-layer A write) ----------------
__global__ void gather_combine(const float* __restrict__ b,
                               const int* __restrict__ batch, int layer, int write_a) {
    int warp = (blockIdx.x * blockDim.x + threadIdx.x) >> 5;
    int lane = threadIdx.x & 31;
    if (warp >= N_NODES) return;

    int s0 = d_rowptr[warp];
    int s1 = d_rowptr[warp + 1];

    float4 acc = make_float4(0.f, 0.f, 0.f, 0.f);
#pragma unroll 4
    for (int j = s0; j < s1; j++) {
        int nb = d_adj[j];
        float4 v = *(const float4*)&d_projL[(size_t)nb * 128 + lane * 4];
        acc.x += v.x; acc.y += v.y; acc.z += v.z; acc.w += v.w;
    }
    float inv = 1.0f / fmaxf((float)(s1 - s0), 1.0f);
    float4 rr = *(const float4*)&d_projR[(size_t)warp * 128 + lane * 4];
    float4 bb = *(const float4*)&b[lane * 4];
    float hv[4];
    hv[0] = acc.x * inv + rr.x + bb.x;
    hv[1] = acc.y * inv + rr.y + bb.y;
    hv[2] = acc.z * inv + rr.z + bb.z;
    hv[3] = acc.w * inv + rr.w + bb.w;

    if (write_a) {
        uint32_t hp[2], lp[2];
#pragma unroll
        for (int p = 0; p < 2; p++) {
            __nv_bfloat16 h0, l0, h1, l1;
            split_bf16(hv[p * 2], h0, l0);
            split_bf16(hv[p * 2 + 1], h1, l1);
            hp[p] = ((uint32_t)__bfloat16_as_ushort(h1) << 16) | __bfloat16_as_ushort(h0);
            lp[p] = ((uint32_t)__bfloat16_as_ushort(l1) << 16) | __bfloat16_as_ushort(l0);
        }
        size_t off = (size_t)warp * STRIDE12 + lane * 4;
        *(uint2*)&d_A12hi[off] = make_uint2(hp[0], hp[1]);
        *(uint2*)&d_A12lo[off] = make_uint2(lp[0], lp[1]);
    }

    unsigned* gp = &d_genc[batch[warp] * HCAT + layer * 128 + lane * 4];
    atomicMax(gp + 0, encf(hv[0]));
    atomicMax(gp + 1, encf(hv[1]));
    atomicMax(gp + 2, encf(hv[2]));
    atomicMax(gp + 3, encf(hv[3]));
}

// ---------------- FC head ----------------
__global__ void fc_kernel(const float* __restrict__ Wfc1, const float* __restrict__ bfc1,
                          const float* __restrict__ Wfc2, const float* __restrict__ bfc2,
                          float* __restrict__ out) {
    __shared__ float g[HCAT];
    __shared__ float z[160];
    int gr = blockIdx.x, t = threadIdx.x;

    for (int i = t; i < HCAT; i += 160) g[i] = decf(d_genc[gr * HCAT + i]);
    __syncthreads();

    float acc = bfc1[t];
#pragma unroll 8
    for (int k = 0; k < HCAT; k++) acc += g[k] * Wfc1[k * 160 + t];
    z[t] = fmaxf(acc, 0.f);
    __syncthreads();

    if (t < 10) {
        float o = bfc2[t];
#pragma unroll 8
        for (int k = 0; k < 160; k++) o += z[k] * Wfc2[k * 10 + t];
        out[gr * 10 + t] = o;
    }
}

// ---------------- launch ----------------
extern "C" void kernel_launch(void* const* d_in, const int* in_sizes, int n_in,
                              void* d_out, int out_size) {
    const float* x     = (const float*)d_in[0];
    const int*   eidx  = (const int*)d_in[1];
    const int*   batch = (const int*)d_in[2];
    const float* info  = (const float*)d_in[3];
    const float* Wl[3] = { (const float*)d_in[4], (const float*)d_in[7],  (const float*)d_in[10] };
    const float* Wr[3] = { (const float*)d_in[5], (const float*)d_in[8],  (const float*)d_in[11] };
    const float* bb[3] = { (const float*)d_in[6], (const float*)d_in[9],  (const float*)d_in[12] };
    const float* Wfc1  = (const float*)d_in[13];
    const float* bfc1  = (const float*)d_in[14];
    const float* Wfc2  = (const float*)d_in[15];
    const float* bfc2  = (const float*)d_in[16];
    float* out = (float*)d_out;

    const int* src = eidx;
    const int* dst = eidx + N_EDGES;
    const int T = 256;

    cudaFuncSetAttribute(sage_gemm, cudaFuncAttributeMaxDynamicSharedMemorySize, SM_TOTAL);

    init_kernel<<<(NUM_GRAPHS * HCAT + T - 1) / T, T>>>();
    deg_kernel<<<(N_EDGES + T - 1) / T, T>>>(dst);
    scan_kernel<<<1, 1024>>>();
    fill_kernel<<<(N_EDGES + T - 1) / T, T>>>(src, dst);
    prep0<<<(N_NODES * 128 + T - 1) / T, T>>>(x, info, batch);
    prepinfo<<<(N_NODES * 32 + T - 1) / T, T>>>(info, batch);
    pack_all<<<(3 * 256 * KPAD + T - 1) / T, T>>>(Wl[0], Wr[0], Wl[1], Wr[1], Wl[2], Wr[2]);

    __nv_bfloat16 *a0h = nullptr, *a0l = nullptr, *a12h = nullptr, *a12l = nullptr;
    __nv_bfloat16 *bhp = nullptr, *blp = nullptr;
    cudaGetSymbolAddress((void**)&a0h, d_A0hi);
    cudaGetSymbolAddress((void**)&a0l, d_A0lo);
    cudaGetSymbolAddress((void**)&a12h, d_A12hi);
    cudaGetSymbolAddress((void**)&a12l, d_A12lo);
    cudaGetSymbolAddress((void**)&bhp, d_Bhi);
    cudaGetSymbolAddress((void**)&blp, d_Blo);

    for (int layer = 0; layer < 3; layer++) {
        int K = (layer == 0) ? 128 : 160;
        int nch = K / 32;
        const __nv_bfloat16* Ah = (layer == 0) ? a0h : a12h;
        const __nv_bfloat16* Al = (layer == 0) ? a0l : a12l;
        int strideA = (layer == 0) ? 128 : STRIDE12;

        sage_gemm<<<dim3((N_NODES + 127) / 128, 2), 256, SM_TOTAL>>>(
            Ah, Al, bhp + layer * 256 * KPAD, blp + layer * 256 * KPAD, strideA, nch);

        gather_combine<<<(N_NODES * 32 + T - 1) / T, T>>>(bb[layer], batch, layer, layer < 2);
    }

    fc_kernel<<<NUM_GRAPHS, 160>>>(Wfc1, bfc1, Wfc2, bfc2, out);
    (void)in_sizes; (void)n_in; (void)out_size;
}

// round 9
// speedup vs baseline: 3.2441x; 1.0978x over previous
#include <cuda_runtime.h>
#include <cuda_fp16.h>
#include <cstdint>

#define N_NODES    50000
#define N_EDGES    800000
#define NUM_GRAPHS 500
#define CONV_OUT   128
#define HCAT       384
#define KPAD       192
#define STRIDE12   192

// ---------------- scratch (static device globals) ----------------
__device__ float     d_projL[N_NODES * CONV_OUT];
__device__ float     d_projR[N_NODES * CONV_OUT];
__device__ int       d_count[N_NODES];
__device__ int       d_rowptr[N_NODES + 1];
__device__ int       d_cursor[N_NODES];
__device__ int       d_adj[N_EDGES];
__device__ unsigned  d_genc[NUM_GRAPHS * HCAT];
__device__ __half    d_B[3 * 256 * KPAD];          // [layer][n][k], single fp16
__device__ __half    d_A0hi[N_NODES * 128];        // layer0 A
__device__ __half    d_A0lo[N_NODES * 128];
__device__ __half    d_A12hi[N_NODES * STRIDE12];  // layers1-2 A
__device__ __half    d_A12lo[N_NODES * STRIDE12];

// monotone float <-> uint encoding for atomicMax on signed floats
__device__ __forceinline__ unsigned encf(float f) {
    unsigned u = __float_as_uint(f);
    return (u & 0x80000000u) ? ~u : (u | 0x80000000u);
}
__device__ __forceinline__ float decf(unsigned u) {
    u = (u & 0x80000000u) ? (u & 0x7FFFFFFFu) : ~u;
    return __uint_as_float(u);
}
#define ENC_NEG_INF 0x007FFFFFu

__device__ __forceinline__ uint32_t smem_u32(const void* p) {
    uint32_t a;
    asm("{ .reg .u64 t; cvta.to.shared.u64 t, %1; cvt.u32.u64 %0, t; }" : "=r"(a) : "l"(p));
    return a;
}

__device__ __forceinline__ void cp16(uint32_t dst, const void* src, bool pred) {
    int sz = pred ? 16 : 0;
    asm volatile("cp.async.cg.shared.global [%0], [%1], 16, %2;"
                 :: "r"(dst), "l"(src), "r"(sz) : "memory");
}
#define CP_COMMIT()  asm volatile("cp.async.commit_group;" ::: "memory")
#define CP_WAIT(n)   asm volatile("cp.async.wait_group %0;" :: "n"(n) : "memory")

#define LDSM_X4(r, addr) \
    asm volatile("ldmatrix.sync.aligned.m8n8.x4.shared.b16 {%0,%1,%2,%3}, [%4];" \
        : "=r"((r)[0]), "=r"((r)[1]), "=r"((r)[2]), "=r"((r)[3]) : "r"(addr))

#define MMA_F16(c, a, b0, b1) \
    asm volatile("mma.sync.aligned.m16n8k16.row.col.f32.f16.f16.f32 " \
        "{%0,%1,%2,%3}, {%4,%5,%6,%7}, {%8,%9}, {%0,%1,%2,%3};" \
        : "+f"((c)[0]), "+f"((c)[1]), "+f"((c)[2]), "+f"((c)[3]) \
        : "r"((a)[0]), "r"((a)[1]), "r"((a)[2]), "r"((a)[3]), "r"(b0), "r"(b1))

__device__ __forceinline__ void split_f16(float v, __half& hi, __half& lo) {
    hi = __float2half(v);
    lo = __float2half(v - __half2float(hi));
}

// ---------------- fused prep: A0 split, A12 info cols, B pack, genc/count init ----------------
#define RP0 (N_NODES * 128)       // 6,400,000
#define RP1 (N_NODES * 32)        // 1,600,000
#define RP2 (3 * 256 * KPAD)      //   147,456
#define RP3 (NUM_GRAPHS * HCAT)   //   192,000
#define RP4 (N_NODES)             //    50,000
#define PREP_TOTAL (RP0 + RP1 + RP2 + RP3 + RP4)

__global__ void prep_fused(const float* __restrict__ x, const float* __restrict__ info,
                           const int* __restrict__ batch,
                           const float* __restrict__ Wl0, const float* __restrict__ Wr0,
                           const float* __restrict__ Wl1, const float* __restrict__ Wr1,
                           const float* __restrict__ Wl2, const float* __restrict__ Wr2) {
    long long i = (long long)blockIdx.x * blockDim.x + threadIdx.x;
    if (i < RP0) {
        int r = (int)(i >> 7), c = (int)(i & 127);
        float v = (c < 96) ? x[r * 96 + c] : info[batch[r] * 32 + (c - 96)];
        __half hi, lo;
        split_f16(v, hi, lo);
        d_A0hi[i] = hi;
        d_A0lo[i] = lo;
        return;
    }
    i -= RP0;
    if (i < RP1) {
        int r = (int)(i >> 5), c = (int)(i & 31);
        float v = info[batch[r] * 32 + c];
        __half hi, lo;
        split_f16(v, hi, lo);
        d_A12hi[r * STRIDE12 + 128 + c] = hi;
        d_A12lo[r * STRIDE12 + 128 + c] = lo;
        return;
    }
    i -= RP1;
    if (i < RP2) {
        int idx = (int)i;
        int layer = idx / (256 * KPAD);
        int rem = idx - layer * (256 * KPAD);
        int n = rem / KPAD, k = rem - n * KPAD;
        int K = (layer == 0) ? 128 : 160;
        const float* Wl = (layer == 0) ? Wl0 : (layer == 1) ? Wl1 : Wl2;
        const float* Wr = (layer == 0) ? Wr0 : (layer == 1) ? Wr1 : Wr2;
        float v = 0.f;
        if (k < K) v = (n < 128) ? Wl[k * 128 + n] : Wr[k * 128 + (n - 128)];
        d_B[idx] = __float2half(v);
        return;
    }
    i -= RP2;
    if (i < RP3) { d_genc[i] = ENC_NEG_INF; return; }
    i -= RP3;
    if (i < RP4) d_count[i] = 0;
}

// ---------------- graph-structure kernels ----------------
__global__ void deg_kernel(const int* __restrict__ dst) {
    int e = blockIdx.x * blockDim.x + threadIdx.x;
    if (e < N_EDGES) atomicAdd(&d_count[dst[e]], 1);
}

__global__ void scan_kernel() {
    __shared__ int s[1024];
    int t = threadIdx.x;
    const int CH = (N_NODES + 1023) / 1024;
    int base = t * CH;
    int lim = min(base + CH, N_NODES);
    int sum = 0;
    for (int i = base; i < lim; i++) sum += d_count[i];
    s[t] = sum;
    __syncthreads();
    for (int off = 1; off < 1024; off <<= 1) {
        int v = (t >= off) ? s[t - off] : 0;
        __syncthreads();
        s[t] += v;
        __syncthreads();
    }
    int run = s[t] - sum;
    for (int i = base; i < lim; i++) {
        d_rowptr[i] = run;
        d_cursor[i] = run;
        run += d_count[i];
    }
    if (t == 1023) d_rowptr[N_NODES] = s[1023];
}

__global__ void fill_kernel(const int* __restrict__ src, const int* __restrict__ dst) {
    int e = blockIdx.x * blockDim.x + threadIdx.x;
    if (e < N_EDGES) {
        int pos = atomicAdd(&d_cursor[dst[e]], 1);
        d_adj[pos] = src[e];
    }
}

// ---------------- fp16 2-term mma.sync GEMM, cp.async 3-stage pipeline ----------------
// C[M,256] = A @ Wcat; grid.y selects N-half (0->projL, 1->projR)
// CTA: 128x128, 8 warps (4M x 2N), warp 32x64. K chunk 32, 3 stages.
#define PITCH 80
#define ST_AHI 0
#define ST_ALO 10240
#define ST_B   20480
#define STAGE  30720
#define SM_TOTAL 92160

__global__ void __launch_bounds__(256, 2)
sage_gemm(const __half* __restrict__ Ahi, const __half* __restrict__ Alo,
          const __half* __restrict__ B, int strideA, int nch) {
    extern __shared__ char smem[];
    uint32_t sb = smem_u32(smem);
    const int M = N_NODES;
    int bm = blockIdx.x * 128;
    int nh = blockIdx.y;
    int tid = threadIdx.x;
    int wid = tid >> 5;
    int lane = tid & 31;
    int wm = wid & 3, wn = wid >> 2;
    int g = lane >> 2, t4 = lane & 3;

    const char* Ahg = (const char*)Ahi;
    const char* Alg = (const char*)Alo;
    const char* Bg  = (const char*)B;

    int r0i = tid >> 2, seg = tid & 3;       // rows 0..63
    int r1i = r0i + 64;                      // rows 64..127
    bool p0 = (bm + r0i) < M;
    bool p1 = (bm + r1i) < M;

    float acc[2][8][4];
#pragma unroll
    for (int mt = 0; mt < 2; mt++)
#pragma unroll
        for (int nt = 0; nt < 8; nt++)
#pragma unroll
            for (int j = 0; j < 4; j++) acc[mt][nt][j] = 0.f;

    auto load_chunk = [&](int s, int kc) {
        int c0 = kc * 32;
        uint32_t st = sb + s * STAGE;
        size_t aoff0 = ((size_t)(bm + r0i) * strideA + c0) * 2 + seg * 16;
        size_t aoff1 = ((size_t)(bm + r1i) * strideA + c0) * 2 + seg * 16;
        uint32_t so0 = r0i * PITCH + seg * 16;
        uint32_t so1 = r1i * PITCH + seg * 16;
        cp16(st + ST_AHI + so0, Ahg + aoff0, p0);
        cp16(st + ST_AHI + so1, Ahg + aoff1, p1);
        cp16(st + ST_ALO + so0, Alg + aoff0, p0);
        cp16(st + ST_ALO + so1, Alg + aoff1, p1);
        size_t boff0 = ((size_t)(nh * 128 + r0i) * KPAD + c0) * 2 + seg * 16;
        size_t boff1 = ((size_t)(nh * 128 + r1i) * KPAD + c0) * 2 + seg * 16;
        cp16(st + ST_B + so0, Bg + boff0, true);
        cp16(st + ST_B + so1, Bg + boff1, true);
    };

    load_chunk(0, 0);
    CP_COMMIT();
    if (nch > 1) load_chunk(1, 1);
    CP_COMMIT();

    uint32_t brow = (lane & 7) + ((lane >> 4) << 3);
    uint32_t bkof = ((lane >> 3) & 1) << 4;

    for (int kc = 0; kc < nch; kc++) {
        // ensure chunk kc's group is complete: at most 1 (the kc+1 prefetch) pending
        if (kc + 1 < nch) {
            CP_WAIT(1);
        } else {
            CP_WAIT(0);
        }
        __syncthreads();
        if (kc + 2 < nch) {
            load_chunk((kc + 2) % 3, kc + 2);
            CP_COMMIT();
        }

        uint32_t st = sb + (kc % 3) * STAGE;
#pragma unroll
        for (int kk = 0; kk < 2; kk++) {
            uint32_t ahi[2][4], alo[2][4], bfr[4][4];
#pragma unroll
            for (int mt = 0; mt < 2; mt++) {
                uint32_t ab = (uint32_t)((wm * 32 + mt * 16 + (lane & 15)) * PITCH
                               + kk * 32 + ((lane >> 4) << 4));
                LDSM_X4(ahi[mt], st + ST_AHI + ab);
                LDSM_X4(alo[mt], st + ST_ALO + ab);
            }
#pragma unroll
            for (int nt2 = 0; nt2 < 4; nt2++) {
                uint32_t bb = (uint32_t)((wn * 64 + nt2 * 16 + brow) * PITCH + kk * 32 + bkof);
                LDSM_X4(bfr[nt2], st + ST_B + bb);
            }
#pragma unroll
            for (int mt = 0; mt < 2; mt++)
#pragma unroll
                for (int nt = 0; nt < 8; nt++) {
                    uint32_t b0 = bfr[nt >> 1][(nt & 1) * 2];
                    uint32_t b1 = bfr[nt >> 1][(nt & 1) * 2 + 1];
                    MMA_F16(acc[mt][nt], ahi[mt], b0, b1);
                    MMA_F16(acc[mt][nt], alo[mt], b0, b1);
                }
        }
        __syncthreads();
    }

    float* outp = (nh == 0) ? d_projL : d_projR;
#pragma unroll
    for (int mt = 0; mt < 2; mt++) {
        int r0 = bm + wm * 32 + mt * 16 + g;
#pragma unroll
        for (int nt = 0; nt < 8; nt++) {
            int col = wn * 64 + nt * 8 + t4 * 2;
            if (r0 < M)
                *(float2*)&outp[(size_t)r0 * 128 + col] =
                    make_float2(acc[mt][nt][0], acc[mt][nt][1]);
            if (r0 + 8 < M)
                *(float2*)&outp[(size_t)(r0 + 8) * 128 + col] =
                    make_float2(acc[mt][nt][2], acc[mt][nt][3]);
        }
    }
}

// ---------------- aggregation + pooling (+ next-layer A write) ----------------
__global__ void gather_combine(const float* __restrict__ b,
                               const int* __restrict__ batch, int layer, int write_a) {
    int warp = (blockIdx.x * blockDim.x + threadIdx.x) >> 5;
    int lane = threadIdx.x & 31;
    if (warp >= N_NODES) return;

    int s0 = d_rowptr[warp];
    int s1 = d_rowptr[warp + 1];

    float4 acc = make_float4(0.f, 0.f, 0.f, 0.f);
#pragma unroll 4
    for (int j = s0; j < s1; j++) {
        int nb = d_adj[j];
        float4 v = *(const float4*)&d_projL[(size_t)nb * 128 + lane * 4];
        acc.x += v.x; acc.y += v.y; acc.z += v.z; acc.w += v.w;
    }
    float inv = 1.0f / fmaxf((float)(s1 - s0), 1.0f);
    float4 rr = *(const float4*)&d_projR[(size_t)warp * 128 + lane * 4];
    float4 bb = *(const float4*)&b[lane * 4];
    float hv[4];
    hv[0] = acc.x * inv + rr.x + bb.x;
    hv[1] = acc.y * inv + rr.y + bb.y;
    hv[2] = acc.z * inv + rr.z + bb.z;
    hv[3] = acc.w * inv + rr.w + bb.w;

    if (write_a) {
        uint32_t hp[2], lp[2];
#pragma unroll
        for (int p = 0; p < 2; p++) {
            __half h0, l0, h1, l1;
            split_f16(hv[p * 2], h0, l0);
            split_f16(hv[p * 2 + 1], h1, l1);
            hp[p] = ((uint32_t)__half_as_ushort(h1) << 16) | __half_as_ushort(h0);
            lp[p] = ((uint32_t)__half_as_ushort(l1) << 16) | __half_as_ushort(l0);
        }
        size_t off = (size_t)warp * STRIDE12 + lane * 4;
        *(uint2*)&d_A12hi[off] = make_uint2(hp[0], hp[1]);
        *(uint2*)&d_A12lo[off] = make_uint2(lp[0], lp[1]);
    }

    unsigned* gp = &d_genc[batch[warp] * HCAT + layer * 128 + lane * 4];
    atomicMax(gp + 0, encf(hv[0]));
    atomicMax(gp + 1, encf(hv[1]));
    atomicMax(gp + 2, encf(hv[2]));
    atomicMax(gp + 3, encf(hv[3]));
}

// ---------------- FC head ----------------
__global__ void fc_kernel(const float* __restrict__ Wfc1, const float* __restrict__ bfc1,
                          const float* __restrict__ Wfc2, const float* __restrict__ bfc2,
                          float* __restrict__ out) {
    __shared__ float g[HCAT];
    __shared__ float z[160];
    int gr = blockIdx.x, t = threadIdx.x;

    for (int i = t; i < HCAT; i += 160) g[i] = decf(d_genc[gr * HCAT + i]);
    __syncthreads();

    float acc = bfc1[t];
#pragma unroll 8
    for (int k = 0; k < HCAT; k++) acc += g[k] * Wfc1[k * 160 + t];
    z[t] = fmaxf(acc, 0.f);
    __syncthreads();

    if (t < 10) {
        float o = bfc2[t];
#pragma unroll 8
        for (int k = 0; k < 160; k++) o += z[k] * Wfc2[k * 10 + t];
        out[gr * 10 + t] = o;
    }
}

// ---------------- launch ----------------
extern "C" void kernel_launch(void* const* d_in, const int* in_sizes, int n_in,
                              void* d_out, int out_size) {
    const float* x     = (const float*)d_in[0];
    const int*   eidx  = (const int*)d_in[1];
    const int*   batch = (const int*)d_in[2];
    const float* info  = (const float*)d_in[3];
    const float* Wl[3] = { (const float*)d_in[4], (const float*)d_in[7],  (const float*)d_in[10] };
    const float* Wr[3] = { (const float*)d_in[5], (const float*)d_in[8],  (const float*)d_in[11] };
    const float* bb[3] = { (const float*)d_in[6], (const float*)d_in[9],  (const float*)d_in[12] };
    const float* Wfc1  = (const float*)d_in[13];
    const float* bfc1  = (const float*)d_in[14];
    const float* Wfc2  = (const float*)d_in[15];
    const float* bfc2  = (const float*)d_in[16];
    float* out = (float*)d_out;

    const int* src = eidx;
    const int* dst = eidx + N_EDGES;
    const int T = 256;

    cudaFuncSetAttribute(sage_gemm, cudaFuncAttributeMaxDynamicSharedMemorySize, SM_TOTAL);

    prep_fused<<<(int)((PREP_TOTAL + T - 1) / T), T>>>(x, info, batch,
        Wl[0], Wr[0], Wl[1], Wr[1], Wl[2], Wr[2]);
    deg_kernel<<<(N_EDGES + T - 1) / T, T>>>(dst);
    scan_kernel<<<1, 1024>>>();
    fill_kernel<<<(N_EDGES + T - 1) / T, T>>>(src, dst);

    __half *a0h = nullptr, *a0l = nullptr, *a12h = nullptr, *a12l = nullptr, *bp = nullptr;
    cudaGetSymbolAddress((void**)&a0h, d_A0hi);
    cudaGetSymbolAddress((void**)&a0l, d_A0lo);
    cudaGetSymbolAddress((void**)&a12h, d_A12hi);
    cudaGetSymbolAddress((void**)&a12l, d_A12lo);
    cudaGetSymbolAddress((void**)&bp, d_B);

    for (int layer = 0; layer < 3; layer++) {
        int K = (layer == 0) ? 128 : 160;
        int nch = K / 32;
        const __half* Ah = (layer == 0) ? a0h : a12h;
        const __half* Al = (layer == 0) ? a0l : a12l;
        int strideA = (layer == 0) ? 128 : STRIDE12;

        sage_gemm<<<dim3((N_NODES + 127) / 128, 2), 256, SM_TOTAL>>>(
            Ah, Al, bp + layer * 256 * KPAD, strideA, nch);

        gather_combine<<<(N_NODES * 32 + T - 1) / T, T>>>(bb[layer], batch, layer, layer < 2);
    }

    fc_kernel<<<NUM_GRAPHS, 160>>>(Wfc1, bfc1, Wfc2, bfc2, out);
    (void)in_sizes; (void)n_in; (void)out_size;
}

// round 10
// speedup vs baseline: 3.3876x; 1.0442x over previous
#include <cuda_runtime.h>
#include <cuda_fp16.h>
#include <cstdint>

#define N_NODES    50000
#define N_EDGES    800000
#define NUM_GRAPHS 500
#define CONV_OUT   128
#define HCAT       384
#define KPAD       192
#define STRIDE12   192

// ---------------- scratch (static device globals) ----------------
__device__ __half    d_projLh[N_NODES * CONV_OUT];   // fp16 projL (gather operand)
__device__ float     d_projR[N_NODES * CONV_OUT];
__device__ int       d_count[N_NODES];
__device__ int       d_rowptr[N_NODES + 1];
__device__ int       d_cursor[N_NODES];
__device__ int       d_adj[N_EDGES];
__device__ unsigned  d_genc[NUM_GRAPHS * HCAT];
__device__ __half    d_B[3 * 256 * KPAD];          // [layer][n][k], single fp16
__device__ __half    d_A0hi[N_NODES * 128];        // layer0 A
__device__ __half    d_A0lo[N_NODES * 128];
__device__ __half    d_A12hi[N_NODES * STRIDE12];  // layers1-2 A
__device__ __half    d_A12lo[N_NODES * STRIDE12];

// monotone float <-> uint encoding for atomicMax on signed floats
__device__ __forceinline__ unsigned encf(float f) {
    unsigned u = __float_as_uint(f);
    return (u & 0x80000000u) ? ~u : (u | 0x80000000u);
}
__device__ __forceinline__ float decf(unsigned u) {
    u = (u & 0x80000000u) ? (u & 0x7FFFFFFFu) : ~u;
    return __uint_as_float(u);
}
#define ENC_NEG_INF 0x007FFFFFu

__device__ __forceinline__ uint32_t smem_u32(const void* p) {
    uint32_t a;
    asm("{ .reg .u64 t; cvta.to.shared.u64 t, %1; cvt.u32.u64 %0, t; }" : "=r"(a) : "l"(p));
    return a;
}

__device__ __forceinline__ void cp16(uint32_t dst, const void* src, bool pred) {
    int sz = pred ? 16 : 0;
    asm volatile("cp.async.cg.shared.global [%0], [%1], 16, %2;"
                 :: "r"(dst), "l"(src), "r"(sz) : "memory");
}
#define CP_COMMIT()  asm volatile("cp.async.commit_group;" ::: "memory")
#define CP_WAIT(n)   asm volatile("cp.async.wait_group %0;" :: "n"(n) : "memory")

#define LDSM_X4(r, addr) \
    asm volatile("ldmatrix.sync.aligned.m8n8.x4.shared.b16 {%0,%1,%2,%3}, [%4];" \
        : "=r"((r)[0]), "=r"((r)[1]), "=r"((r)[2]), "=r"((r)[3]) : "r"(addr))

#define MMA_F16(c, a, b0, b1) \
    asm volatile("mma.sync.aligned.m16n8k16.row.col.f32.f16.f16.f32 " \
        "{%0,%1,%2,%3}, {%4,%5,%6,%7}, {%8,%9}, {%0,%1,%2,%3};" \
        : "+f"((c)[0]), "+f"((c)[1]), "+f"((c)[2]), "+f"((c)[3]) \
        : "r"((a)[0]), "r"((a)[1]), "r"((a)[2]), "r"((a)[3]), "r"(b0), "r"(b1))

__device__ __forceinline__ void split_f16(float v, __half& hi, __half& lo) {
    hi = __float2half(v);
    lo = __float2half(v - __half2float(hi));
}

// ---------------- fused prep: A0 split, A12 info cols, B pack, genc/count init ----------------
#define RP0 (N_NODES * 128)
#define RP1 (N_NODES * 32)
#define RP2 (3 * 256 * KPAD)
#define RP3 (NUM_GRAPHS * HCAT)
#define RP4 (N_NODES)
#define PREP_TOTAL (RP0 + RP1 + RP2 + RP3 + RP4)

__global__ void prep_fused(const float* __restrict__ x, const float* __restrict__ info,
                           const int* __restrict__ batch,
                           const float* __restrict__ Wl0, const float* __restrict__ Wr0,
                           const float* __restrict__ Wl1, const float* __restrict__ Wr1,
                           const float* __restrict__ Wl2, const float* __restrict__ Wr2) {
    long long i = (long long)blockIdx.x * blockDim.x + threadIdx.x;
    if (i < RP0) {
        int r = (int)(i >> 7), c = (int)(i & 127);
        float v = (c < 96) ? x[r * 96 + c] : info[batch[r] * 32 + (c - 96)];
        __half hi, lo;
        split_f16(v, hi, lo);
        d_A0hi[i] = hi;
        d_A0lo[i] = lo;
        return;
    }
    i -= RP0;
    if (i < RP1) {
        int r = (int)(i >> 5), c = (int)(i & 31);
        float v = info[batch[r] * 32 + c];
        __half hi, lo;
        split_f16(v, hi, lo);
        d_A12hi[r * STRIDE12 + 128 + c] = hi;
        d_A12lo[r * STRIDE12 + 128 + c] = lo;
        return;
    }
    i -= RP1;
    if (i < RP2) {
        int idx = (int)i;
        int layer = idx / (256 * KPAD);
        int rem = idx - layer * (256 * KPAD);
        int n = rem / KPAD, k = rem - n * KPAD;
        int K = (layer == 0) ? 128 : 160;
        const float* Wl = (layer == 0) ? Wl0 : (layer == 1) ? Wl1 : Wl2;
        const float* Wr = (layer == 0) ? Wr0 : (layer == 1) ? Wr1 : Wr2;
        float v = 0.f;
        if (k < K) v = (n < 128) ? Wl[k * 128 + n] : Wr[k * 128 + (n - 128)];
        d_B[idx] = __float2half(v);
        return;
    }
    i -= RP2;
    if (i < RP3) { d_genc[i] = ENC_NEG_INF; return; }
    i -= RP3;
    if (i < RP4) d_count[i] = 0;
}

// ---------------- graph-structure kernels ----------------
__global__ void deg_kernel(const int* __restrict__ dst) {
    int e = blockIdx.x * blockDim.x + threadIdx.x;
    if (e < N_EDGES) atomicAdd(&d_count[dst[e]], 1);
}

__global__ void scan_kernel() {
    __shared__ int s[1024];
    int t = threadIdx.x;
    const int CH = (N_NODES + 1023) / 1024;
    int base = t * CH;
    int lim = min(base + CH, N_NODES);
    int sum = 0;
    for (int i = base; i < lim; i++) sum += d_count[i];
    s[t] = sum;
    __syncthreads();
    for (int off = 1; off < 1024; off <<= 1) {
        int v = (t >= off) ? s[t - off] : 0;
        __syncthreads();
        s[t] += v;
        __syncthreads();
    }
    int run = s[t] - sum;
    for (int i = base; i < lim; i++) {
        d_rowptr[i] = run;
        d_cursor[i] = run;
        run += d_count[i];
    }
    if (t == 1023) d_rowptr[N_NODES] = s[1023];
}

__global__ void fill_kernel(const int* __restrict__ src, const int* __restrict__ dst) {
    int e = blockIdx.x * blockDim.x + threadIdx.x;
    if (e < N_EDGES) {
        int pos = atomicAdd(&d_cursor[dst[e]], 1);
        d_adj[pos] = src[e];
    }
}

// ---------------- fp16 2-term mma.sync GEMM, cp.async 3-stage pipeline ----------------
#define PITCH 80
#define ST_AHI 0
#define ST_ALO 10240
#define ST_B   20480
#define STAGE  30720
#define SM_TOTAL 92160

__global__ void __launch_bounds__(256, 2)
sage_gemm(const __half* __restrict__ Ahi, const __half* __restrict__ Alo,
          const __half* __restrict__ B, int strideA, int nch) {
    extern __shared__ char smem[];
    uint32_t sb = smem_u32(smem);
    const int M = N_NODES;
    int bm = blockIdx.x * 128;
    int nh = blockIdx.y;
    int tid = threadIdx.x;
    int wid = tid >> 5;
    int lane = tid & 31;
    int wm = wid & 3, wn = wid >> 2;
    int g = lane >> 2, t4 = lane & 3;

    const char* Ahg = (const char*)Ahi;
    const char* Alg = (const char*)Alo;
    const char* Bg  = (const char*)B;

    int r0i = tid >> 2, seg = tid & 3;
    int r1i = r0i + 64;
    bool p0 = (bm + r0i) < M;
    bool p1 = (bm + r1i) < M;

    float acc[2][8][4];
#pragma unroll
    for (int mt = 0; mt < 2; mt++)
#pragma unroll
        for (int nt = 0; nt < 8; nt++)
#pragma unroll
            for (int j = 0; j < 4; j++) acc[mt][nt][j] = 0.f;

    auto load_chunk = [&](int s, int kc) {
        int c0 = kc * 32;
        uint32_t st = sb + s * STAGE;
        size_t aoff0 = ((size_t)(bm + r0i) * strideA + c0) * 2 + seg * 16;
        size_t aoff1 = ((size_t)(bm + r1i) * strideA + c0) * 2 + seg * 16;
        uint32_t so0 = r0i * PITCH + seg * 16;
        uint32_t so1 = r1i * PITCH + seg * 16;
        cp16(st + ST_AHI + so0, Ahg + aoff0, p0);
        cp16(st + ST_AHI + so1, Ahg + aoff1, p1);
        cp16(st + ST_ALO + so0, Alg + aoff0, p0);
        cp16(st + ST_ALO + so1, Alg + aoff1, p1);
        size_t boff0 = ((size_t)(nh * 128 + r0i) * KPAD + c0) * 2 + seg * 16;
        size_t boff1 = ((size_t)(nh * 128 + r1i) * KPAD + c0) * 2 + seg * 16;
        cp16(st + ST_B + so0, Bg + boff0, true);
        cp16(st + ST_B + so1, Bg + boff1, true);
    };

    load_chunk(0, 0);
    CP_COMMIT();
    if (nch > 1) load_chunk(1, 1);
    CP_COMMIT();

    uint32_t brow = (lane & 7) + ((lane >> 4) << 3);
    uint32_t bkof = ((lane >> 3) & 1) << 4;

    for (int kc = 0; kc < nch; kc++) {
        if (kc + 1 < nch) {
            CP_WAIT(1);
        } else {
            CP_WAIT(0);
        }
        __syncthreads();
        if (kc + 2 < nch) {
            load_chunk((kc + 2) % 3, kc + 2);
            CP_COMMIT();
        }

        uint32_t st = sb + (kc % 3) * STAGE;
#pragma unroll
        for (int kk = 0; kk < 2; kk++) {
            uint32_t ahi[2][4], alo[2][4], bfr[4][4];
#pragma unroll
            for (int mt = 0; mt < 2; mt++) {
                uint32_t ab = (uint32_t)((wm * 32 + mt * 16 + (lane & 15)) * PITCH
                               + kk * 32 + ((lane >> 4) << 4));
                LDSM_X4(ahi[mt], st + ST_AHI + ab);
                LDSM_X4(alo[mt], st + ST_ALO + ab);
            }
#pragma unroll
            for (int nt2 = 0; nt2 < 4; nt2++) {
                uint32_t bb = (uint32_t)((wn * 64 + nt2 * 16 + brow) * PITCH + kk * 32 + bkof);
                LDSM_X4(bfr[nt2], st + ST_B + bb);
            }
#pragma unroll
            for (int mt = 0; mt < 2; mt++)
#pragma unroll
                for (int nt = 0; nt < 8; nt++) {
                    uint32_t b0 = bfr[nt >> 1][(nt & 1) * 2];
                    uint32_t b1 = bfr[nt >> 1][(nt & 1) * 2 + 1];
                    MMA_F16(acc[mt][nt], ahi[mt], b0, b1);
                    MMA_F16(acc[mt][nt], alo[mt], b0, b1);
                }
        }
        __syncthreads();
    }

    // epilogue: nh==0 -> fp16 projL (gather operand), nh==1 -> fp32 projR
    if (nh == 0) {
#pragma unroll
        for (int mt = 0; mt < 2; mt++) {
            int r0 = bm + wm * 32 + mt * 16 + g;
#pragma unroll
            for (int nt = 0; nt < 8; nt++) {
                int col = wn * 64 + nt * 8 + t4 * 2;
                if (r0 < M)
                    *(__half2*)&d_projLh[(size_t)r0 * 128 + col] =
                        __floats2half2_rn(acc[mt][nt][0], acc[mt][nt][1]);
                if (r0 + 8 < M)
                    *(__half2*)&d_projLh[(size_t)(r0 + 8) * 128 + col] =
                        __floats2half2_rn(acc[mt][nt][2], acc[mt][nt][3]);
            }
        }
    } else {
#pragma unroll
        for (int mt = 0; mt < 2; mt++) {
            int r0 = bm + wm * 32 + mt * 16 + g;
#pragma unroll
            for (int nt = 0; nt < 8; nt++) {
                int col = wn * 64 + nt * 8 + t4 * 2;
                if (r0 < M)
                    *(float2*)&d_projR[(size_t)r0 * 128 + col] =
                        make_float2(acc[mt][nt][0], acc[mt][nt][1]);
                if (r0 + 8 < M)
                    *(float2*)&d_projR[(size_t)(r0 + 8) * 128 + col] =
                        make_float2(acc[mt][nt][2], acc[mt][nt][3]);
            }
        }
    }
}

// ---------------- aggregation + pooling (+ next-layer A write) ----------------
__global__ void gather_combine(const float* __restrict__ b,
                               const int* __restrict__ batch, int layer, int write_a) {
    int warp = (blockIdx.x * blockDim.x + threadIdx.x) >> 5;
    int lane = threadIdx.x & 31;
    if (warp >= N_NODES) return;

    int s0 = d_rowptr[warp];
    int s1 = d_rowptr[warp + 1];

    float acc0 = 0.f, acc1 = 0.f, acc2 = 0.f, acc3 = 0.f;
#pragma unroll 4
    for (int j = s0; j < s1; j++) {
        int nb = d_adj[j];
        uint2 v = *(const uint2*)&d_projLh[(size_t)nb * 128 + lane * 4];
        float2 f0 = __half22float2(*(__half2*)&v.x);
        float2 f1 = __half22float2(*(__half2*)&v.y);
        acc0 += f0.x; acc1 += f0.y; acc2 += f1.x; acc3 += f1.y;
    }
    float inv = 1.0f / fmaxf((float)(s1 - s0), 1.0f);
    float4 rr = *(const float4*)&d_projR[(size_t)warp * 128 + lane * 4];
    float4 bb = *(const float4*)&b[lane * 4];
    float hv[4];
    hv[0] = acc0 * inv + rr.x + bb.x;
    hv[1] = acc1 * inv + rr.y + bb.y;
    hv[2] = acc2 * inv + rr.z + bb.z;
    hv[3] = acc3 * inv + rr.w + bb.w;

    if (write_a) {
        uint32_t hp[2], lp[2];
#pragma unroll
        for (int p = 0; p < 2; p++) {
            __half h0, l0, h1, l1;
            split_f16(hv[p * 2], h0, l0);
            split_f16(hv[p * 2 + 1], h1, l1);
            hp[p] = ((uint32_t)__half_as_ushort(h1) << 16) | __half_as_ushort(h0);
            lp[p] = ((uint32_t)__half_as_ushort(l1) << 16) | __half_as_ushort(l0);
        }
        size_t off = (size_t)warp * STRIDE12 + lane * 4;
        *(uint2*)&d_A12hi[off] = make_uint2(hp[0], hp[1]);
        *(uint2*)&d_A12lo[off] = make_uint2(lp[0], lp[1]);
    }

    unsigned* gp = &d_genc[batch[warp] * HCAT + layer * 128 + lane * 4];
    atomicMax(gp + 0, encf(hv[0]));
    atomicMax(gp + 1, encf(hv[1]));
    atomicMax(gp + 2, encf(hv[2]));
    atomicMax(gp + 3, encf(hv[3]));
}

// ---------------- FC head ----------------
__global__ void fc_kernel(const float* __restrict__ Wfc1, const float* __restrict__ bfc1,
                          const float* __restrict__ Wfc2, const float* __restrict__ bfc2,
                          float* __restrict__ out) {
    __shared__ float g[HCAT];
    __shared__ float z[160];
    int gr = blockIdx.x, t = threadIdx.x;

    for (int i = t; i < HCAT; i += 160) g[i] = decf(d_genc[gr * HCAT + i]);
    __syncthreads();

    float acc = bfc1[t];
#pragma unroll 8
    for (int k = 0; k < HCAT; k++) acc += g[k] * Wfc1[k * 160 + t];
    z[t] = fmaxf(acc, 0.f);
    __syncthreads();

    if (t < 10) {
        float o = bfc2[t];
#pragma unroll 8
        for (int k = 0; k < 160; k++) o += z[k] * Wfc2[k * 10 + t];
        out[gr * 10 + t] = o;
    }
}

// ---------------- launch ----------------
extern "C" void kernel_launch(void* const* d_in, const int* in_sizes, int n_in,
                              void* d_out, int out_size) {
    const float* x     = (const float*)d_in[0];
    const int*   eidx  = (const int*)d_in[1];
    const int*   batch = (const int*)d_in[2];
    const float* info  = (const float*)d_in[3];
    const float* Wl[3] = { (const float*)d_in[4], (const float*)d_in[7],  (const float*)d_in[10] };
    const float* Wr[3] = { (const float*)d_in[5], (const float*)d_in[8],  (const float*)d_in[11] };
    const float* bb[3] = { (const float*)d_in[6], (const float*)d_in[9],  (const float*)d_in[12] };
    const float* Wfc1  = (const float*)d_in[13];
    const float* bfc1  = (const float*)d_in[14];
    const float* Wfc2  = (const float*)d_in[15];
    const float* bfc2  = (const float*)d_in[16];
    float* out = (float*)d_out;

    const int* src = eidx;
    const int* dst = eidx + N_EDGES;
    const int T = 256;

    cudaFuncSetAttribute(sage_gemm, cudaFuncAttributeMaxDynamicSharedMemorySize, SM_TOTAL);

    prep_fused<<<(int)((PREP_TOTAL + T - 1) / T), T>>>(x, info, batch,
        Wl[0], Wr[0], Wl[1], Wr[1], Wl[2], Wr[2]);
    deg_kernel<<<(N_EDGES + T - 1) / T, T>>>(dst);
    scan_kernel<<<1, 1024>>>();
    fill_kernel<<<(N_EDGES + T - 1) / T, T>>>(src, dst);

    __half *a0h = nullptr, *a0l = nullptr, *a12h = nullptr, *a12l = nullptr, *bp = nullptr;
    cudaGetSymbolAddress((void**)&a0h, d_A0hi);
    cudaGetSymbolAddress((void**)&a0l, d_A0lo);
    cudaGetSymbolAddress((void**)&a12h, d_A12hi);
    cudaGetSymbolAddress((void**)&a12l, d_A12lo);
    cudaGetSymbolAddress((void**)&bp, d_B);

    for (int layer = 0; layer < 3; layer++) {
        int K = (layer == 0) ? 128 : 160;
        int nch = K / 32;
        const __half* Ah = (layer == 0) ? a0h : a12h;
        const __half* Al = (layer == 0) ? a0l : a12l;
        int strideA = (layer == 0) ? 128 : STRIDE12;

        sage_gemm<<<dim3((N_NODES + 127) / 128, 2), 256, SM_TOTAL>>>(
            Ah, Al, bp + layer * 256 * KPAD, strideA, nch);

        gather_combine<<<(N_NODES * 32 + T - 1) / T, T>>>(bb[layer], batch, layer, layer < 2);
    }

    fc_kernel<<<NUM_GRAPHS, 160>>>(Wfc1, bfc1, Wfc2, bfc2, out);
    (void)in_sizes; (void)n_in; (void)out_size;
}

// round 11
// speedup vs baseline: 3.6796x; 1.0862x over previous
#include <cuda_runtime.h>
#include <cuda_fp16.h>
#include <cstdint>

#define N_NODES    50000
#define N_EDGES    800000
#define NUM_GRAPHS 500
#define CONV_OUT   128
#define HCAT       384
#define KPAD       192
#define STRIDE12   192

// ---------------- scratch (static device globals) ----------------
__device__ __half    d_projLh[N_NODES * CONV_OUT];   // fp16 projL (gather operand)
__device__ float     d_projR[N_NODES * CONV_OUT];
__device__ int       d_count[N_NODES];
__device__ int       d_rowptr[N_NODES + 1];
__device__ int       d_cursor[N_NODES];
__device__ int       d_adj[N_EDGES];
__device__ unsigned  d_genc[NUM_GRAPHS * HCAT];
__device__ __half    d_B[3 * 256 * KPAD];          // [layer][n][k], single fp16
__device__ __half    d_A0hi[N_NODES * 128];        // layer0 A
__device__ __half    d_A0lo[N_NODES * 128];
__device__ __half    d_A12hi[N_NODES * STRIDE12];  // layers1-2 A
__device__ __half    d_A12lo[N_NODES * STRIDE12];

// monotone float <-> uint encoding for atomicMax on signed floats
__device__ __forceinline__ unsigned encf(float f) {
    unsigned u = __float_as_uint(f);
    return (u & 0x80000000u) ? ~u : (u | 0x80000000u);
}
__device__ __forceinline__ float decf(unsigned u) {
    u = (u & 0x80000000u) ? (u & 0x7FFFFFFFu) : ~u;
    return __uint_as_float(u);
}
#define ENC_NEG_INF 0x007FFFFFu

__device__ __forceinline__ uint32_t smem_u32(const void* p) {
    uint32_t a;
    asm("{ .reg .u64 t; cvta.to.shared.u64 t, %1; cvt.u32.u64 %0, t; }" : "=r"(a) : "l"(p));
    return a;
}

__device__ __forceinline__ void cp16(uint32_t dst, const void* src, bool pred) {
    int sz = pred ? 16 : 0;
    asm volatile("cp.async.cg.shared.global [%0], [%1], 16, %2;"
                 :: "r"(dst), "l"(src), "r"(sz) : "memory");
}
#define CP_COMMIT()  asm volatile("cp.async.commit_group;" ::: "memory")
#define CP_WAIT(n)   asm volatile("cp.async.wait_group %0;" :: "n"(n) : "memory")

#define LDSM_X4(r, addr) \
    asm volatile("ldmatrix.sync.aligned.m8n8.x4.shared.b16 {%0,%1,%2,%3}, [%4];" \
        : "=r"((r)[0]), "=r"((r)[1]), "=r"((r)[2]), "=r"((r)[3]) : "r"(addr))

#define MMA_F16(c, a, b0, b1) \
    asm volatile("mma.sync.aligned.m16n8k16.row.col.f32.f16.f16.f32 " \
        "{%0,%1,%2,%3}, {%4,%5,%6,%7}, {%8,%9}, {%0,%1,%2,%3};" \
        : "+f"((c)[0]), "+f"((c)[1]), "+f"((c)[2]), "+f"((c)[3]) \
        : "r"((a)[0]), "r"((a)[1]), "r"((a)[2]), "r"((a)[3]), "r"(b0), "r"(b1))

__device__ __forceinline__ void split_f16(float v, __half& hi, __half& lo) {
    hi = __float2half(v);
    lo = __float2half(v - __half2float(hi));
}

// ---------------- fused prep: A0 split, A12 info cols, B pack, genc/count init ----------------
#define RP0 (N_NODES * 128)
#define RP1 (N_NODES * 32)
#define RP2 (3 * 256 * KPAD)
#define RP3 (NUM_GRAPHS * HCAT)
#define RP4 (N_NODES)
#define PREP_TOTAL (RP0 + RP1 + RP2 + RP3 + RP4)

__global__ void prep_fused(const float* __restrict__ x, const float* __restrict__ info,
                           const int* __restrict__ batch,
                           const float* __restrict__ Wl0, const float* __restrict__ Wr0,
                           const float* __restrict__ Wl1, const float* __restrict__ Wr1,
                           const float* __restrict__ Wl2, const float* __restrict__ Wr2) {
    long long i = (long long)blockIdx.x * blockDim.x + threadIdx.x;
    if (i < RP0) {
        int r = (int)(i >> 7), c = (int)(i & 127);
        float v = (c < 96) ? x[r * 96 + c] : info[batch[r] * 32 + (c - 96)];
        __half hi, lo;
        split_f16(v, hi, lo);
        d_A0hi[i] = hi;
        d_A0lo[i] = lo;
        return;
    }
    i -= RP0;
    if (i < RP1) {
        int r = (int)(i >> 5), c = (int)(i & 31);
        float v = info[batch[r] * 32 + c];
        __half hi, lo;
        split_f16(v, hi, lo);
        d_A12hi[r * STRIDE12 + 128 + c] = hi;
        d_A12lo[r * STRIDE12 + 128 + c] = lo;
        return;
    }
    i -= RP1;
    if (i < RP2) {
        int idx = (int)i;
        int layer = idx / (256 * KPAD);
        int rem = idx - layer * (256 * KPAD);
        int n = rem / KPAD, k = rem - n * KPAD;
        int K = (layer == 0) ? 128 : 160;
        const float* Wl = (layer == 0) ? Wl0 : (layer == 1) ? Wl1 : Wl2;
        const float* Wr = (layer == 0) ? Wr0 : (layer == 1) ? Wr1 : Wr2;
        float v = 0.f;
        if (k < K) v = (n < 128) ? Wl[k * 128 + n] : Wr[k * 128 + (n - 128)];
        d_B[idx] = __float2half(v);
        return;
    }
    i -= RP2;
    if (i < RP3) { d_genc[i] = ENC_NEG_INF; return; }
    i -= RP3;
    if (i < RP4) d_count[i] = 0;
}

// ---------------- graph-structure kernels ----------------
__global__ void deg_kernel(const int* __restrict__ dst) {
    int e = blockIdx.x * blockDim.x + threadIdx.x;
    if (e < N_EDGES) atomicAdd(&d_count[dst[e]], 1);
}

__global__ void scan_kernel() {
    __shared__ int s[1024];
    int t = threadIdx.x;
    const int CH = (N_NODES + 1023) / 1024;
    int base = t * CH;
    int lim = min(base + CH, N_NODES);
    int sum = 0;
    for (int i = base; i < lim; i++) sum += d_count[i];
    s[t] = sum;
    __syncthreads();
    for (int off = 1; off < 1024; off <<= 1) {
        int v = (t >= off) ? s[t - off] : 0;
        __syncthreads();
        s[t] += v;
        __syncthreads();
    }
    int run = s[t] - sum;
    for (int i = base; i < lim; i++) {
        d_rowptr[i] = run;
        d_cursor[i] = run;
        run += d_count[i];
    }
    if (t == 1023) d_rowptr[N_NODES] = s[1023];
}

__global__ void fill_kernel(const int* __restrict__ src, const int* __restrict__ dst) {
    int e = blockIdx.x * blockDim.x + threadIdx.x;
    if (e < N_EDGES) {
        int pos = atomicAdd(&d_cursor[dst[e]], 1);
        d_adj[pos] = src[e];
    }
}

// ---------------- fp16 2-term mma.sync GEMM, cp.async 3-stage pipeline ----------------
#define PITCH 80
#define ST_AHI 0
#define ST_ALO 10240
#define ST_B   20480
#define STAGE  30720
#define SM_TOTAL 92160

__global__ void __launch_bounds__(256, 2)
sage_gemm(const __half* __restrict__ Ahi, const __half* __restrict__ Alo,
          const __half* __restrict__ B, int strideA, int nch) {
    extern __shared__ char smem[];
    uint32_t sb = smem_u32(smem);
    const int M = N_NODES;
    int bm = blockIdx.x * 128;
    int nh = blockIdx.y;
    int tid = threadIdx.x;
    int wid = tid >> 5;
    int lane = tid & 31;
    int wm = wid & 3, wn = wid >> 2;
    int g = lane >> 2, t4 = lane & 3;

    const char* Ahg = (const char*)Ahi;
    const char* Alg = (const char*)Alo;
    const char* Bg  = (const char*)B;

    int r0i = tid >> 2, seg = tid & 3;
    int r1i = r0i + 64;
    bool p0 = (bm + r0i) < M;
    bool p1 = (bm + r1i) < M;

    float acc[2][8][4];
#pragma unroll
    for (int mt = 0; mt < 2; mt++)
#pragma unroll
        for (int nt = 0; nt < 8; nt++)
#pragma unroll
            for (int j = 0; j < 4; j++) acc[mt][nt][j] = 0.f;

    auto load_chunk = [&](int s, int kc) {
        int c0 = kc * 32;
        uint32_t st = sb + s * STAGE;
        size_t aoff0 = ((size_t)(bm + r0i) * strideA + c0) * 2 + seg * 16;
        size_t aoff1 = ((size_t)(bm + r1i) * strideA + c0) * 2 + seg * 16;
        uint32_t so0 = r0i * PITCH + seg * 16;
        uint32_t so1 = r1i * PITCH + seg * 16;
        cp16(st + ST_AHI + so0, Ahg + aoff0, p0);
        cp16(st + ST_AHI + so1, Ahg + aoff1, p1);
        cp16(st + ST_ALO + so0, Alg + aoff0, p0);
        cp16(st + ST_ALO + so1, Alg + aoff1, p1);
        size_t boff0 = ((size_t)(nh * 128 + r0i) * KPAD + c0) * 2 + seg * 16;
        size_t boff1 = ((size_t)(nh * 128 + r1i) * KPAD + c0) * 2 + seg * 16;
        cp16(st + ST_B + so0, Bg + boff0, true);
        cp16(st + ST_B + so1, Bg + boff1, true);
    };

    load_chunk(0, 0);
    CP_COMMIT();
    if (nch > 1) load_chunk(1, 1);
    CP_COMMIT();

    uint32_t brow = (lane & 7) + ((lane >> 4) << 3);
    uint32_t bkof = ((lane >> 3) & 1) << 4;

    for (int kc = 0; kc < nch; kc++) {
        if (kc + 1 < nch) {
            CP_WAIT(1);
        } else {
            CP_WAIT(0);
        }
        __syncthreads();
        if (kc + 2 < nch) {
            load_chunk((kc + 2) % 3, kc + 2);
            CP_COMMIT();
        }

        uint32_t st = sb + (kc % 3) * STAGE;
#pragma unroll
        for (int kk = 0; kk < 2; kk++) {
            uint32_t ahi[2][4], alo[2][4], bfr[4][4];
#pragma unroll
            for (int mt = 0; mt < 2; mt++) {
                uint32_t ab = (uint32_t)((wm * 32 + mt * 16 + (lane & 15)) * PITCH
                               + kk * 32 + ((lane >> 4) << 4));
                LDSM_X4(ahi[mt], st + ST_AHI + ab);
                LDSM_X4(alo[mt], st + ST_ALO + ab);
            }
#pragma unroll
            for (int nt2 = 0; nt2 < 4; nt2++) {
                uint32_t bb = (uint32_t)((wn * 64 + nt2 * 16 + brow) * PITCH + kk * 32 + bkof);
                LDSM_X4(bfr[nt2], st + ST_B + bb);
            }
#pragma unroll
            for (int mt = 0; mt < 2; mt++)
#pragma unroll
                for (int nt = 0; nt < 8; nt++) {
                    uint32_t b0 = bfr[nt >> 1][(nt & 1) * 2];
                    uint32_t b1 = bfr[nt >> 1][(nt & 1) * 2 + 1];
                    MMA_F16(acc[mt][nt], ahi[mt], b0, b1);
                    MMA_F16(acc[mt][nt], alo[mt], b0, b1);
                }
        }
        __syncthreads();
    }

    // epilogue: nh==0 -> fp16 projL (gather operand), nh==1 -> fp32 projR
    if (nh == 0) {
#pragma unroll
        for (int mt = 0; mt < 2; mt++) {
            int r0 = bm + wm * 32 + mt * 16 + g;
#pragma unroll
            for (int nt = 0; nt < 8; nt++) {
                int col = wn * 64 + nt * 8 + t4 * 2;
                if (r0 < M)
                    *(__half2*)&d_projLh[(size_t)r0 * 128 + col] =
                        __floats2half2_rn(acc[mt][nt][0], acc[mt][nt][1]);
                if (r0 + 8 < M)
                    *(__half2*)&d_projLh[(size_t)(r0 + 8) * 128 + col] =
                        __floats2half2_rn(acc[mt][nt][2], acc[mt][nt][3]);
            }
        }
    } else {
#pragma unroll
        for (int mt = 0; mt < 2; mt++) {
            int r0 = bm + wm * 32 + mt * 16 + g;
#pragma unroll
            for (int nt = 0; nt < 8; nt++) {
                int col = wn * 64 + nt * 8 + t4 * 2;
                if (r0 < M)
                    *(float2*)&d_projR[(size_t)r0 * 128 + col] =
                        make_float2(acc[mt][nt][0], acc[mt][nt][1]);
                if (r0 + 8 < M)
                    *(float2*)&d_projR[(size_t)(r0 + 8) * 128 + col] =
                        make_float2(acc[mt][nt][2], acc[mt][nt][3]);
            }
        }
    }
}

// ---------------- aggregation + pooling (+ next-layer A write) ----------------
// 512 threads = 16 warps = 16 consecutive nodes per block; block-level max
// pre-reduction in smem exploits sorted batch (few graph runs per block),
// cutting global atomicMax count ~14x.
#define GNODES 16
__global__ void __launch_bounds__(512)
gather_combine(const float* __restrict__ b, const int* __restrict__ batch,
               int layer, int write_a) {
    __shared__ float sv[GNODES][CONV_OUT];
    __shared__ int   sbat[GNODES];

    int tid = threadIdx.x;
    int wid = tid >> 5;
    int lane = tid & 31;
    int node = blockIdx.x * GNODES + wid;
    bool valid = (node < N_NODES);

    if (valid) {
        int s0 = d_rowptr[node];
        int s1 = d_rowptr[node + 1];

        float acc0 = 0.f, acc1 = 0.f, acc2 = 0.f, acc3 = 0.f;
#pragma unroll 4
        for (int j = s0; j < s1; j++) {
            int nb = d_adj[j];
            uint2 v = *(const uint2*)&d_projLh[(size_t)nb * 128 + lane * 4];
            float2 f0 = __half22float2(*(__half2*)&v.x);
            float2 f1 = __half22float2(*(__half2*)&v.y);
            acc0 += f0.x; acc1 += f0.y; acc2 += f1.x; acc3 += f1.y;
        }
        float inv = 1.0f / fmaxf((float)(s1 - s0), 1.0f);
        float4 rr = *(const float4*)&d_projR[(size_t)node * 128 + lane * 4];
        float4 bb = *(const float4*)&b[lane * 4];
        float hv[4];
        hv[0] = acc0 * inv + rr.x + bb.x;
        hv[1] = acc1 * inv + rr.y + bb.y;
        hv[2] = acc2 * inv + rr.z + bb.z;
        hv[3] = acc3 * inv + rr.w + bb.w;

        if (write_a) {
            uint32_t hp[2], lp[2];
#pragma unroll
            for (int p = 0; p < 2; p++) {
                __half h0, l0, h1, l1;
                split_f16(hv[p * 2], h0, l0);
                split_f16(hv[p * 2 + 1], h1, l1);
                hp[p] = ((uint32_t)__half_as_ushort(h1) << 16) | __half_as_ushort(h0);
                lp[p] = ((uint32_t)__half_as_ushort(l1) << 16) | __half_as_ushort(l0);
            }
            size_t off = (size_t)node * STRIDE12 + lane * 4;
            *(uint2*)&d_A12hi[off] = make_uint2(hp[0], hp[1]);
            *(uint2*)&d_A12lo[off] = make_uint2(lp[0], lp[1]);
        }

        *(float4*)&sv[wid][lane * 4] = make_float4(hv[0], hv[1], hv[2], hv[3]);
        if (lane == 0) sbat[wid] = batch[node];
    } else {
        if (lane == 0) sbat[wid] = -1;
    }
    __syncthreads();

    // threads 0..127: column-wise run-max over the 16 nodes, one atomic per run
    if (tid < CONV_OUT) {
        int col = tid;
        int cur = -1;
        float mx = 0.f;
#pragma unroll
        for (int i = 0; i < GNODES; i++) {
            int bt = sbat[i];
            if (bt != cur) {
                if (cur >= 0)
                    atomicMax(&d_genc[cur * HCAT + layer * 128 + col], encf(mx));
                cur = bt;
                mx = -3.4e38f;
            }
            if (bt >= 0) mx = fmaxf(mx, sv[i][col]);
        }
        if (cur >= 0)
            atomicMax(&d_genc[cur * HCAT + layer * 128 + col], encf(mx));
    }
}

// ---------------- FC head ----------------
__global__ void fc_kernel(const float* __restrict__ Wfc1, const float* __restrict__ bfc1,
                          const float* __restrict__ Wfc2, const float* __restrict__ bfc2,
                          float* __restrict__ out) {
    __shared__ float g[HCAT];
    __shared__ float z[160];
    int gr = blockIdx.x, t = threadIdx.x;

    for (int i = t; i < HCAT; i += 160) g[i] = decf(d_genc[gr * HCAT + i]);
    __syncthreads();

    float acc = bfc1[t];
#pragma unroll 8
    for (int k = 0; k < HCAT; k++) acc += g[k] * Wfc1[k * 160 + t];
    z[t] = fmaxf(acc, 0.f);
    __syncthreads();

    if (t < 10) {
        float o = bfc2[t];
#pragma unroll 8
        for (int k = 0; k < 160; k++) o += z[k] * Wfc2[k * 10 + t];
        out[gr * 10 + t] = o;
    }
}

// ---------------- launch ----------------
extern "C" void kernel_launch(void* const* d_in, const int* in_sizes, int n_in,
                              void* d_out, int out_size) {
    const float* x     = (const float*)d_in[0];
    const int*   eidx  = (const int*)d_in[1];
    const int*   batch = (const int*)d_in[2];
    const float* info  = (const float*)d_in[3];
    const float* Wl[3] = { (const float*)d_in[4], (const float*)d_in[7],  (const float*)d_in[10] };
    const float* Wr[3] = { (const float*)d_in[5], (const float*)d_in[8],  (const float*)d_in[11] };
    const float* bb[3] = { (const float*)d_in[6], (const float*)d_in[9],  (const float*)d_in[12] };
    const float* Wfc1  = (const float*)d_in[13];
    const float* bfc1  = (const float*)d_in[14];
    const float* Wfc2  = (const float*)d_in[15];
    const float* bfc2  = (const float*)d_in[16];
    float* out = (float*)d_out;

    const int* src = eidx;
    const int* dst = eidx + N_EDGES;
    const int T = 256;

    cudaFuncSetAttribute(sage_gemm, cudaFuncAttributeMaxDynamicSharedMemorySize, SM_TOTAL);

    prep_fused<<<(int)((PREP_TOTAL + T - 1) / T), T>>>(x, info, batch,
        Wl[0], Wr[0], Wl[1], Wr[1], Wl[2], Wr[2]);
    deg_kernel<<<(N_EDGES + T - 1) / T, T>>>(dst);
    scan_kernel<<<1, 1024>>>();
    fill_kernel<<<(N_EDGES + T - 1) / T, T>>>(src, dst);

    __half *a0h = nullptr, *a0l = nullptr, *a12h = nullptr, *a12l = nullptr, *bp = nullptr;
    cudaGetSymbolAddress((void**)&a0h, d_A0hi);
    cudaGetSymbolAddress((void**)&a0l, d_A0lo);
    cudaGetSymbolAddress((void**)&a12h, d_A12hi);
    cudaGetSymbolAddress((void**)&a12l, d_A12lo);
    cudaGetSymbolAddress((void**)&bp, d_B);

    for (int layer = 0; layer < 3; layer++) {
        int K = (layer == 0) ? 128 : 160;
        int nch = K / 32;
        const __half* Ah = (layer == 0) ? a0h : a12h;
        const __half* Al = (layer == 0) ? a0l : a12l;
        int strideA = (layer == 0) ? 128 : STRIDE12;

        sage_gemm<<<dim3((N_NODES + 127) / 128, 2), 256, SM_TOTAL>>>(
            Ah, Al, bp + layer * 256 * KPAD, strideA, nch);

        gather_combine<<<(N_NODES + GNODES - 1) / GNODES, 512>>>(bb[layer], batch, layer, layer < 2);
    }

    fc_kernel<<<NUM_GRAPHS, 160>>>(Wfc1, bfc1, Wfc2, bfc2, out);
    (void)in_sizes; (void)n_in; (void)out_size;
}

// round 13
// speedup vs baseline: 4.0544x; 1.1019x over previous
#include <cuda_runtime.h>
#include <cuda_fp16.h>
#include <cstdint>

#define N_NODES    50000
#define N_EDGES    800000
#define NUM_GRAPHS 500
#define CONV_OUT   128
#define HCAT       384
#define KPAD       192
#define STRIDE12   192

// ---------------- scratch (static device globals) ----------------
__device__ __half    d_projLh[N_NODES * CONV_OUT];   // fp16 projL (gather operand)
__device__ float     d_projR[N_NODES * CONV_OUT];
__device__ int       d_count[N_NODES];
__device__ int       d_rowptr[N_NODES + 1];
__device__ int       d_cursor[N_NODES];
__device__ int       d_adj[N_EDGES];
__device__ unsigned  d_genc[NUM_GRAPHS * HCAT];
__device__ __half    d_B[3 * 256 * KPAD];          // [layer][n][k], fp16
__device__ __half    d_A0[N_NODES * 128];          // layer0 A (fp16)
__device__ __half    d_A12[N_NODES * STRIDE12];    // layers1-2 A (fp16)

// monotone float <-> uint encoding for atomicMax on signed floats
__device__ __forceinline__ unsigned encf(float f) {
    unsigned u = __float_as_uint(f);
    return (u & 0x80000000u) ? ~u : (u | 0x80000000u);
}
__device__ __forceinline__ float decf(unsigned u) {
    u = (u & 0x80000000u) ? (u & 0x7FFFFFFFu) : ~u;
    return __uint_as_float(u);
}
#define ENC_NEG_INF 0x007FFFFFu

__device__ __forceinline__ uint32_t smem_u32(const void* p) {
    uint32_t a;
    asm("{ .reg .u64 t; cvta.to.shared.u64 t, %1; cvt.u32.u64 %0, t; }" : "=r"(a) : "l"(p));
    return a;
}

__device__ __forceinline__ void cp16(uint32_t dst, const void* src, bool pred) {
    int sz = pred ? 16 : 0;
    asm volatile("cp.async.cg.shared.global [%0], [%1], 16, %2;"
                 :: "r"(dst), "l"(src), "r"(sz) : "memory");
}
#define CP_COMMIT()  asm volatile("cp.async.commit_group;" ::: "memory")
#define CP_WAIT(n)   asm volatile("cp.async.wait_group %0;" :: "n"(n) : "memory")

#define LDSM_X4(r, addr) \
    asm volatile("ldmatrix.sync.aligned.m8n8.x4.shared.b16 {%0,%1,%2,%3}, [%4];" \
        : "=r"((r)[0]), "=r"((r)[1]), "=r"((r)[2]), "=r"((r)[3]) : "r"(addr))

#define MMA_F16(c, a, b0, b1) \
    asm volatile("mma.sync.aligned.m16n8k16.row.col.f32.f16.f16.f32 " \
        "{%0,%1,%2,%3}, {%4,%5,%6,%7}, {%8,%9}, {%0,%1,%2,%3};" \
        : "+f"((c)[0]), "+f"((c)[1]), "+f"((c)[2]), "+f"((c)[3]) \
        : "r"((a)[0]), "r"((a)[1]), "r"((a)[2]), "r"((a)[3]), "r"(b0), "r"(b1))

// ---------------- fused prep: A0, A12 info cols, B pack, genc/count init ----------------
#define RP0 (N_NODES * 128)
#define RP1 (N_NODES * 32)
#define RP2 (3 * 256 * KPAD)
#define RP3 (NUM_GRAPHS * HCAT)
#define RP4 (N_NODES)
#define PREP_TOTAL (RP0 + RP1 + RP2 + RP3 + RP4)

__global__ void prep_fused(const float* __restrict__ x, const float* __restrict__ info,
                           const int* __restrict__ batch,
                           const float* __restrict__ Wl0, const float* __restrict__ Wr0,
                           const float* __restrict__ Wl1, const float* __restrict__ Wr1,
                           const float* __restrict__ Wl2, const float* __restrict__ Wr2) {
    long long i = (long long)blockIdx.x * blockDim.x + threadIdx.x;
    if (i < RP0) {
        int r = (int)(i >> 7), c = (int)(i & 127);
        float v = (c < 96) ? x[r * 96 + c] : info[batch[r] * 32 + (c - 96)];
        d_A0[i] = __float2half(v);
        return;
    }
    i -= RP0;
    if (i < RP1) {
        int r = (int)(i >> 5), c = (int)(i & 31);
        d_A12[r * STRIDE12 + 128 + c] = __float2half(info[batch[r] * 32 + c]);
        return;
    }
    i -= RP1;
    if (i < RP2) {
        int idx = (int)i;
        int layer = idx / (256 * KPAD);
        int rem = idx - layer * (256 * KPAD);
        int n = rem / KPAD, k = rem - n * KPAD;
        int K = (layer == 0) ? 128 : 160;
        const float* Wl = (layer == 0) ? Wl0 : (layer == 1) ? Wl1 : Wl2;
        const float* Wr = (layer == 0) ? Wr0 : (layer == 1) ? Wr1 : Wr2;
        float v = 0.f;
        if (k < K) v = (n < 128) ? Wl[k * 128 + n] : Wr[k * 128 + (n - 128)];
        d_B[idx] = __float2half(v);
        return;
    }
    i -= RP2;
    if (i < RP3) { d_genc[i] = ENC_NEG_INF; return; }
    i -= RP3;
    if (i < RP4) d_count[i] = 0;
}

// ---------------- graph-structure kernels ----------------
__global__ void deg_kernel(const int* __restrict__ dst) {
    int e = blockIdx.x * blockDim.x + threadIdx.x;
    if (e < N_EDGES) atomicAdd(&d_count[dst[e]], 1);
}

__global__ void scan_kernel() {
    __shared__ int s[1024];
    int t = threadIdx.x;
    const int CH = (N_NODES + 1023) / 1024;
    int base = t * CH;
    int lim = min(base + CH, N_NODES);
    int sum = 0;
    for (int i = base; i < lim; i++) sum += d_count[i];
    s[t] = sum;
    __syncthreads();
    for (int off = 1; off < 1024; off <<= 1) {
        int v = (t >= off) ? s[t - off] : 0;
        __syncthreads();
        s[t] += v;
        __syncthreads();
    }
    int run = s[t] - sum;
    for (int i = base; i < lim; i++) {
        d_rowptr[i] = run;
        d_cursor[i] = run;
        run += d_count[i];
    }
    if (t == 1023) d_rowptr[N_NODES] = s[1023];
}

__global__ void fill_kernel(const int* __restrict__ src, const int* __restrict__ dst) {
    int e = blockIdx.x * blockDim.x + threadIdx.x;
    if (e < N_EDGES) {
        int pos = atomicAdd(&d_cursor[dst[e]], 1);
        d_adj[pos] = src[e];
    }
}

// ---------------- fp16 single-term mma.sync GEMM, cp.async 3-stage pipeline ----------------
// C[M,256] = A @ Wcat; grid.y selects N-half (0->projL fp16, 1->projR fp32)
// CTA: 128x128, 8 warps (4M x 2N), warp 32x64. K chunk 32, 3 stages.
#define PITCH 80
#define ST_A   0
#define ST_B   10240
#define STAGE  20480
#define SM_TOTAL 61440

__global__ void __launch_bounds__(256, 2)
sage_gemm(const __half* __restrict__ A, const __half* __restrict__ B,
          int strideA, int nch) {
    extern __shared__ char smem[];
    uint32_t sb = smem_u32(smem);
    const int M = N_NODES;
    int bm = blockIdx.x * 128;
    int nh = blockIdx.y;
    int tid = threadIdx.x;
    int wid = tid >> 5;
    int lane = tid & 31;
    int wm = wid & 3, wn = wid >> 2;
    int g = lane >> 2, t4 = lane & 3;

    const char* Ag = (const char*)A;
    const char* Bg = (const char*)B;

    int r0i = tid >> 2, seg = tid & 3;
    int r1i = r0i + 64;
    bool p0 = (bm + r0i) < M;
    bool p1 = (bm + r1i) < M;

    float acc[2][8][4];
#pragma unroll
    for (int mt = 0; mt < 2; mt++)
#pragma unroll
        for (int nt = 0; nt < 8; nt++)
#pragma unroll
            for (int j = 0; j < 4; j++) acc[mt][nt][j] = 0.f;

    auto load_chunk = [&](int s, int kc) {
        int c0 = kc * 32;
        uint32_t st = sb + s * STAGE;
        size_t aoff0 = ((size_t)(bm + r0i) * strideA + c0) * 2 + seg * 16;
        size_t aoff1 = ((size_t)(bm + r1i) * strideA + c0) * 2 + seg * 16;
        uint32_t so0 = r0i * PITCH + seg * 16;
        uint32_t so1 = r1i * PITCH + seg * 16;
        cp16(st + ST_A + so0, Ag + aoff0, p0);
        cp16(st + ST_A + so1, Ag + aoff1, p1);
        size_t boff0 = ((size_t)(nh * 128 + r0i) * KPAD + c0) * 2 + seg * 16;
        size_t boff1 = ((size_t)(nh * 128 + r1i) * KPAD + c0) * 2 + seg * 16;
        cp16(st + ST_B + so0, Bg + boff0, true);
        cp16(st + ST_B + so1, Bg + boff1, true);
    };

    load_chunk(0, 0);
    CP_COMMIT();
    if (nch > 1) load_chunk(1, 1);
    CP_COMMIT();

    uint32_t brow = (lane & 7) + ((lane >> 4) << 3);
    uint32_t bkof = ((lane >> 3) & 1) << 4;

    for (int kc = 0; kc < nch; kc++) {
        if (kc + 1 < nch) {
            CP_WAIT(1);
        } else {
            CP_WAIT(0);
        }
        __syncthreads();
        if (kc + 2 < nch) {
            load_chunk((kc + 2) % 3, kc + 2);
            CP_COMMIT();
        }

        uint32_t st = sb + (kc % 3) * STAGE;
#pragma unroll
        for (int kk = 0; kk < 2; kk++) {
            uint32_t afr[2][4], bfr[4][4];
#pragma unroll
            for (int mt = 0; mt < 2; mt++) {
                uint32_t ab = (uint32_t)((wm * 32 + mt * 16 + (lane & 15)) * PITCH
                               + kk * 32 + ((lane >> 4) << 4));
                LDSM_X4(afr[mt], st + ST_A + ab);
            }
#pragma unroll
            for (int nt2 = 0; nt2 < 4; nt2++) {
                uint32_t bb = (uint32_t)((wn * 64 + nt2 * 16 + brow) * PITCH + kk * 32 + bkof);
                LDSM_X4(bfr[nt2], st + ST_B + bb);
            }
#pragma unroll
            for (int mt = 0; mt < 2; mt++)
#pragma unroll
                for (int nt = 0; nt < 8; nt++) {
                    uint32_t b0 = bfr[nt >> 1][(nt & 1) * 2];
                    uint32_t b1 = bfr[nt >> 1][(nt & 1) * 2 + 1];
                    MMA_F16(acc[mt][nt], afr[mt], b0, b1);
                }
        }
        __syncthreads();
    }

    // epilogue: nh==0 -> fp16 projL (gather operand), nh==1 -> fp32 projR
    if (nh == 0) {
#pragma unroll
        for (int mt = 0; mt < 2; mt++) {
            int r0 = bm + wm * 32 + mt * 16 + g;
#pragma unroll
            for (int nt = 0; nt < 8; nt++) {
                int col = wn * 64 + nt * 8 + t4 * 2;
                if (r0 < M)
                    *(__half2*)&d_projLh[(size_t)r0 * 128 + col] =
                        __floats2half2_rn(acc[mt][nt][0], acc[mt][nt][1]);
                if (r0 + 8 < M)
                    *(__half2*)&d_projLh[(size_t)(r0 + 8) * 128 + col] =
                        __floats2half2_rn(acc[mt][nt][2], acc[mt][nt][3]);
            }
        }
    } else {
#pragma unroll
        for (int mt = 0; mt < 2; mt++) {
            int r0 = bm + wm * 32 + mt * 16 + g;
#pragma unroll
            for (int nt = 0; nt < 8; nt++) {
                int col = wn * 64 + nt * 8 + t4 * 2;
                if (r0 < M)
                    *(float2*)&d_projR[(size_t)r0 * 128 + col] =
                        make_float2(acc[mt][nt][0], acc[mt][nt][1]);
                if (r0 + 8 < M)
                    *(float2*)&d_projR[(size_t)(r0 + 8) * 128 + col] =
                        make_float2(acc[mt][nt][2], acc[mt][nt][3]);
            }
        }
    }
}

// ---------------- aggregation + pooling (+ next-layer A write) ----------------
// 512 threads = 16 warps = 16 consecutive nodes per block; block-level run-max
// pre-reduction exploits sorted batch, ~14x fewer global atomics.
#define GNODES 16
__global__ void __launch_bounds__(512)
gather_combine(const float* __restrict__ b, const int* __restrict__ batch,
               int layer, int write_a) {
    __shared__ float sv[GNODES][CONV_OUT];
    __shared__ int   sbat[GNODES];

    int tid = threadIdx.x;
    int wid = tid >> 5;
    int lane = tid & 31;
    int node = blockIdx.x * GNODES + wid;
    bool valid = (node < N_NODES);

    if (valid) {
        int s0 = d_rowptr[node];
        int s1 = d_rowptr[node + 1];

        float acc0 = 0.f, acc1 = 0.f, acc2 = 0.f, acc3 = 0.f;
#pragma unroll 4
        for (int j = s0; j < s1; j++) {
            int nb = d_adj[j];
            uint2 v = *(const uint2*)&d_projLh[(size_t)nb * 128 + lane * 4];
            float2 f0 = __half22float2(*(__half2*)&v.x);
            float2 f1 = __half22float2(*(__half2*)&v.y);
            acc0 += f0.x; acc1 += f0.y; acc2 += f1.x; acc3 += f1.y;
        }
        float inv = 1.0f / fmaxf((float)(s1 - s0), 1.0f);
        float4 rr = *(const float4*)&d_projR[(size_t)node * 128 + lane * 4];
        float4 bb = *(const float4*)&b[lane * 4];
        float hv[4];
        hv[0] = acc0 * inv + rr.x + bb.x;
        hv[1] = acc1 * inv + rr.y + bb.y;
        hv[2] = acc2 * inv + rr.z + bb.z;
        hv[3] = acc3 * inv + rr.w + bb.w;

        if (write_a) {
            __half2 h0 = __floats2half2_rn(hv[0], hv[1]);
            __half2 h1 = __floats2half2_rn(hv[2], hv[3]);
            size_t off = (size_t)node * STRIDE12 + lane * 4;
            *(__half2*)&d_A12[off]     = h0;
            *(__half2*)&d_A12[off + 2] = h1;
        }

        *(float4*)&sv[wid][lane * 4] = make_float4(hv[0], hv[1], hv[2], hv[3]);
        if (lane == 0) sbat[wid] = batch[node];
    } else {
        if (lane == 0) sbat[wid] = -1;
    }
    __syncthreads();

    if (tid < CONV_OUT) {
        int col = tid;
        int cur = -1;
        float mx = 0.f;
#pragma unroll
        for (int i = 0; i < GNODES; i++) {
            int bt = sbat[i];
            if (bt != cur) {
                if (cur >= 0)
                    atomicMax(&d_genc[cur * HCAT + layer * 128 + col], encf(mx));
                cur = bt;
                mx = -3.4e38f;
            }
            if (bt >= 0) mx = fmaxf(mx, sv[i][col]);
        }
        if (cur >= 0)
            atomicMax(&d_genc[cur * HCAT + layer * 128 + col], encf(mx));
    }
}

// ---------------- FC head ----------------
__global__ void fc_kernel(const float* __restrict__ Wfc1, const float* __restrict__ bfc1,
                          const float* __restrict__ Wfc2, const float* __restrict__ bfc2,
                          float* __restrict__ out) {
    __shared__ float g[HCAT];
    __shared__ float z[160];
    int gr = blockIdx.x, t = threadIdx.x;

    for (int i = t; i < HCAT; i += 160) g[i] = decf(d_genc[gr * HCAT + i]);
    __syncthreads();

    float acc = bfc1[t];
#pragma unroll 8
    for (int k = 0; k < HCAT; k++) acc += g[k] * Wfc1[k * 160 + t];
    z[t] = fmaxf(acc, 0.f);
    __syncthreads();

    if (t < 10) {
        float o = bfc2[t];
#pragma unroll 8
        for (int k = 0; k < 160; k++) o += z[k] * Wfc2[k * 10 + t];
        out[gr * 10 + t] = o;
    }
}

// ---------------- launch ----------------
extern "C" void kernel_launch(void* const* d_in, const int* in_sizes, int n_in,
                              void* d_out, int out_size) {
    const float* x     = (const float*)d_in[0];
    const int*   eidx  = (const int*)d_in[1];
    const int*   batch = (const int*)d_in[2];
    const float* info  = (const float*)d_in[3];
    const float* Wl[3] = { (const float*)d_in[4], (const float*)d_in[7],  (const float*)d_in[10] };
    const float* Wr[3] = { (const float*)d_in[5], (const float*)d_in[8],  (const float*)d_in[11] };
    const float* bb[3] = { (const float*)d_in[6], (const float*)d_in[9],  (const float*)d_in[12] };
    const float* Wfc1  = (const float*)d_in[13];
    const float* bfc1  = (const float*)d_in[14];
    const float* Wfc2  = (const float*)d_in[15];
    const float* bfc2  = (const float*)d_in[16];
    float* out = (float*)d_out;

    const int* src = eidx;
    const int* dst = eidx + N_EDGES;
    const int T = 256;

    cudaFuncSetAttribute(sage_gemm, cudaFuncAttributeMaxDynamicSharedMemorySize, SM_TOTAL);

    prep_fused<<<(int)((PREP_TOTAL + T - 1) / T), T>>>(x, info, batch,
        Wl[0], Wr[0], Wl[1], Wr[1], Wl[2], Wr[2]);
    deg_kernel<<<(N_EDGES + T - 1) / T, T>>>(dst);
    scan_kernel<<<1, 1024>>>();
    fill_kernel<<<(N_EDGES + T - 1) / T, T>>>(src, dst);

    __half *a0 = nullptr, *a12 = nullptr, *bp = nullptr;
    cudaGetSymbolAddress((void**)&a0, d_A0);
    cudaGetSymbolAddress((void**)&a12, d_A12);
    cudaGetSymbolAddress((void**)&bp, d_B);

    for (int layer = 0; layer < 3; layer++) {
        int K = (layer == 0) ? 128 : 160;
        int nch = K / 32;
        const __half* A = (layer == 0) ? a0 : a12;
        int strideA = (layer == 0) ? 128 : STRIDE12;

        sage_gemm<<<dim3((N_NODES + 127) / 128, 2), 256, SM_TOTAL>>>(
            A, bp + layer * 256 * KPAD, strideA, nch);

        gather_combine<<<(N_NODES + GNODES - 1) / GNODES, 512>>>(bb[layer], batch, layer, layer < 2);
    }

    fc_kernel<<<NUM_GRAPHS, 160>>>(Wfc1, bfc1, Wfc2, bfc2, out);
    (void)in_sizes; (void)n_in; (void)out_size;
}

// round 14
// speedup vs baseline: 4.2530x; 1.0490x over previous
#include <cuda_runtime.h>
#include <cuda_fp16.h>
#include <cstdint>

#define N_NODES    50000
#define N_EDGES    800000
#define NUM_GRAPHS 500
#define CONV_OUT   128
#define HCAT       384
#define KPAD       192
#define STRIDE12   192

// ---------------- scratch (static device globals) ----------------
__device__ __half    d_projLh[N_NODES * CONV_OUT];   // fp16 projL (gather operand)
__device__ __half    d_projRh[N_NODES * CONV_OUT];   // fp16 projR
__device__ int       d_count[N_NODES];
__device__ int       d_rowptr[N_NODES + 1];
__device__ int       d_cursor[N_NODES];
__device__ int       d_adj[N_EDGES];
__device__ unsigned  d_genc[NUM_GRAPHS * HCAT];
__device__ __half    d_B[3 * 256 * KPAD];          // [layer][n][k], fp16
__device__ __half    d_A0[N_NODES * 128];          // layer0 A (fp16)
__device__ __half    d_A12[N_NODES * STRIDE12];    // layers1-2 A (fp16)

// monotone float <-> uint encoding for atomicMax on signed floats
__device__ __forceinline__ unsigned encf(float f) {
    unsigned u = __float_as_uint(f);
    return (u & 0x80000000u) ? ~u : (u | 0x80000000u);
}
__device__ __forceinline__ float decf(unsigned u) {
    u = (u & 0x80000000u) ? (u & 0x7FFFFFFFu) : ~u;
    return __uint_as_float(u);
}
#define ENC_NEG_INF 0x007FFFFFu

__device__ __forceinline__ uint32_t smem_u32(const void* p) {
    uint32_t a;
    asm("{ .reg .u64 t; cvta.to.shared.u64 t, %1; cvt.u32.u64 %0, t; }" : "=r"(a) : "l"(p));
    return a;
}

__device__ __forceinline__ void cp16(uint32_t dst, const void* src, bool pred) {
    int sz = pred ? 16 : 0;
    asm volatile("cp.async.cg.shared.global [%0], [%1], 16, %2;"
                 :: "r"(dst), "l"(src), "r"(sz) : "memory");
}
#define CP_COMMIT()  asm volatile("cp.async.commit_group;" ::: "memory")
#define CP_WAIT(n)   asm volatile("cp.async.wait_group %0;" :: "n"(n) : "memory")

#define LDSM_X4(r, addr) \
    asm volatile("ldmatrix.sync.aligned.m8n8.x4.shared.b16 {%0,%1,%2,%3}, [%4];" \
        : "=r"((r)[0]), "=r"((r)[1]), "=r"((r)[2]), "=r"((r)[3]) : "r"(addr))

#define MMA_F16(c, a, b0, b1) \
    asm volatile("mma.sync.aligned.m16n8k16.row.col.f32.f16.f16.f32 " \
        "{%0,%1,%2,%3}, {%4,%5,%6,%7}, {%8,%9}, {%0,%1,%2,%3};" \
        : "+f"((c)[0]), "+f"((c)[1]), "+f"((c)[2]), "+f"((c)[3]) \
        : "r"((a)[0]), "r"((a)[1]), "r"((a)[2]), "r"((a)[3]), "r"(b0), "r"(b1))

// ---------------- fused prep (half2-vectorized A regions) ----------------
#define RP0 (N_NODES * 64)        // A0: 128 cols / 2 per thread
#define RP1 (N_NODES * 16)        // A12 info: 32 cols / 2 per thread
#define RP2 (3 * 256 * KPAD)
#define RP3 (NUM_GRAPHS * HCAT)
#define RP4 (N_NODES)
#define PREP_TOTAL (RP0 + RP1 + RP2 + RP3 + RP4)

__global__ void prep_fused(const float* __restrict__ x, const float* __restrict__ info,
                           const int* __restrict__ batch,
                           const float* __restrict__ Wl0, const float* __restrict__ Wr0,
                           const float* __restrict__ Wl1, const float* __restrict__ Wr1,
                           const float* __restrict__ Wl2, const float* __restrict__ Wr2) {
    long long i = (long long)blockIdx.x * blockDim.x + threadIdx.x;
    if (i < RP0) {
        int r = (int)(i >> 6), c = (int)(i & 63) * 2;   // c even, pair {c, c+1}
        float2 v;
        if (c < 96) v = *(const float2*)&x[r * 96 + c];
        else        v = *(const float2*)&info[batch[r] * 32 + (c - 96)];
        *(__half2*)&d_A0[(size_t)r * 128 + c] = __floats2half2_rn(v.x, v.y);
        return;
    }
    i -= RP0;
    if (i < RP1) {
        int r = (int)(i >> 4), c = (int)(i & 15) * 2;
        float2 v = *(const float2*)&info[batch[r] * 32 + c];
        *(__half2*)&d_A12[(size_t)r * STRIDE12 + 128 + c] = __floats2half2_rn(v.x, v.y);
        return;
    }
    i -= RP1;
    if (i < RP2) {
        int idx = (int)i;
        int layer = idx / (256 * KPAD);
        int rem = idx - layer * (256 * KPAD);
        int n = rem / KPAD, k = rem - n * KPAD;
        int K = (layer == 0) ? 128 : 160;
        const float* Wl = (layer == 0) ? Wl0 : (layer == 1) ? Wl1 : Wl2;
        const float* Wr = (layer == 0) ? Wr0 : (layer == 1) ? Wr1 : Wr2;
        float v = 0.f;
        if (k < K) v = (n < 128) ? Wl[k * 128 + n] : Wr[k * 128 + (n - 128)];
        d_B[idx] = __float2half(v);
        return;
    }
    i -= RP2;
    if (i < RP3) { d_genc[i] = ENC_NEG_INF; return; }
    i -= RP3;
    if (i < RP4) d_count[i] = 0;
}

// ---------------- graph-structure kernels (4-edge ILP) ----------------
__global__ void deg_kernel(const int* __restrict__ dst) {
    int e0 = (blockIdx.x * blockDim.x + threadIdx.x) * 4;
    if (e0 + 3 < N_EDGES) {
        int4 d = *(const int4*)&dst[e0];
        atomicAdd(&d_count[d.x], 1);
        atomicAdd(&d_count[d.y], 1);
        atomicAdd(&d_count[d.z], 1);
        atomicAdd(&d_count[d.w], 1);
    } else {
        for (int e = e0; e < N_EDGES; e++) atomicAdd(&d_count[dst[e]], 1);
    }
}

__global__ void scan_kernel() {
    __shared__ int s[1024];
    int t = threadIdx.x;
    const int CH = (N_NODES + 1023) / 1024;
    int base = t * CH;
    int lim = min(base + CH, N_NODES);
    int sum = 0;
    for (int i = base; i < lim; i++) sum += d_count[i];
    s[t] = sum;
    __syncthreads();
    for (int off = 1; off < 1024; off <<= 1) {
        int v = (t >= off) ? s[t - off] : 0;
        __syncthreads();
        s[t] += v;
        __syncthreads();
    }
    int run = s[t] - sum;
    for (int i = base; i < lim; i++) {
        d_rowptr[i] = run;
        d_cursor[i] = run;
        run += d_count[i];
    }
    if (t == 1023) d_rowptr[N_NODES] = s[1023];
}

__global__ void fill_kernel(const int* __restrict__ src, const int* __restrict__ dst) {
    int e0 = (blockIdx.x * blockDim.x + threadIdx.x) * 4;
    if (e0 + 3 < N_EDGES) {
        int4 d = *(const int4*)&dst[e0];
        int4 sv = *(const int4*)&src[e0];
        int p0 = atomicAdd(&d_cursor[d.x], 1);
        int p1 = atomicAdd(&d_cursor[d.y], 1);
        int p2 = atomicAdd(&d_cursor[d.z], 1);
        int p3 = atomicAdd(&d_cursor[d.w], 1);
        d_adj[p0] = sv.x;
        d_adj[p1] = sv.y;
        d_adj[p2] = sv.z;
        d_adj[p3] = sv.w;
    } else {
        for (int e = e0; e < N_EDGES; e++) {
            int pos = atomicAdd(&d_cursor[dst[e]], 1);
            d_adj[pos] = src[e];
        }
    }
}

// ---------------- fp16 single-term mma.sync GEMM, cp.async 3-stage pipeline ----------------
// C[M,256] = A @ Wcat; grid.y selects N-half (0->projL, 1->projR), both fp16 out
#define PITCH 80
#define ST_A   0
#define ST_B   10240
#define STAGE  20480
#define SM_TOTAL 61440

__global__ void __launch_bounds__(256, 2)
sage_gemm(const __half* __restrict__ A, const __half* __restrict__ B,
          int strideA, int nch) {
    extern __shared__ char smem[];
    uint32_t sb = smem_u32(smem);
    const int M = N_NODES;
    int bm = blockIdx.x * 128;
    int nh = blockIdx.y;
    int tid = threadIdx.x;
    int wid = tid >> 5;
    int lane = tid & 31;
    int wm = wid & 3, wn = wid >> 2;
    int g = lane >> 2, t4 = lane & 3;

    const char* Ag = (const char*)A;
    const char* Bg = (const char*)B;

    int r0i = tid >> 2, seg = tid & 3;
    int r1i = r0i + 64;
    bool p0 = (bm + r0i) < M;
    bool p1 = (bm + r1i) < M;

    float acc[2][8][4];
#pragma unroll
    for (int mt = 0; mt < 2; mt++)
#pragma unroll
        for (int nt = 0; nt < 8; nt++)
#pragma unroll
            for (int j = 0; j < 4; j++) acc[mt][nt][j] = 0.f;

    auto load_chunk = [&](int s, int kc) {
        int c0 = kc * 32;
        uint32_t st = sb + s * STAGE;
        size_t aoff0 = ((size_t)(bm + r0i) * strideA + c0) * 2 + seg * 16;
        size_t aoff1 = ((size_t)(bm + r1i) * strideA + c0) * 2 + seg * 16;
        uint32_t so0 = r0i * PITCH + seg * 16;
        uint32_t so1 = r1i * PITCH + seg * 16;
        cp16(st + ST_A + so0, Ag + aoff0, p0);
        cp16(st + ST_A + so1, Ag + aoff1, p1);
        size_t boff0 = ((size_t)(nh * 128 + r0i) * KPAD + c0) * 2 + seg * 16;
        size_t boff1 = ((size_t)(nh * 128 + r1i) * KPAD + c0) * 2 + seg * 16;
        cp16(st + ST_B + so0, Bg + boff0, true);
        cp16(st + ST_B + so1, Bg + boff1, true);
    };

    load_chunk(0, 0);
    CP_COMMIT();
    if (nch > 1) load_chunk(1, 1);
    CP_COMMIT();

    uint32_t brow = (lane & 7) + ((lane >> 4) << 3);
    uint32_t bkof = ((lane >> 3) & 1) << 4;

    for (int kc = 0; kc < nch; kc++) {
        if (kc + 1 < nch) {
            CP_WAIT(1);
        } else {
            CP_WAIT(0);
        }
        __syncthreads();
        if (kc + 2 < nch) {
            load_chunk((kc + 2) % 3, kc + 2);
            CP_COMMIT();
        }

        uint32_t st = sb + (kc % 3) * STAGE;
#pragma unroll
        for (int kk = 0; kk < 2; kk++) {
            uint32_t afr[2][4], bfr[4][4];
#pragma unroll
            for (int mt = 0; mt < 2; mt++) {
                uint32_t ab = (uint32_t)((wm * 32 + mt * 16 + (lane & 15)) * PITCH
                               + kk * 32 + ((lane >> 4) << 4));
                LDSM_X4(afr[mt], st + ST_A + ab);
            }
#pragma unroll
            for (int nt2 = 0; nt2 < 4; nt2++) {
                uint32_t bb = (uint32_t)((wn * 64 + nt2 * 16 + brow) * PITCH + kk * 32 + bkof);
                LDSM_X4(bfr[nt2], st + ST_B + bb);
            }
#pragma unroll
            for (int mt = 0; mt < 2; mt++)
#pragma unroll
                for (int nt = 0; nt < 8; nt++) {
                    uint32_t b0 = bfr[nt >> 1][(nt & 1) * 2];
                    uint32_t b1 = bfr[nt >> 1][(nt & 1) * 2 + 1];
                    MMA_F16(acc[mt][nt], afr[mt], b0, b1);
                }
        }
        __syncthreads();
    }

    // epilogue: fp16 stores for both halves
    __half* outp = (nh == 0) ? d_projLh : d_projRh;
#pragma unroll
    for (int mt = 0; mt < 2; mt++) {
        int r0 = bm + wm * 32 + mt * 16 + g;
#pragma unroll
        for (int nt = 0; nt < 8; nt++) {
            int col = wn * 64 + nt * 8 + t4 * 2;
            if (r0 < M)
                *(__half2*)&outp[(size_t)r0 * 128 + col] =
                    __floats2half2_rn(acc[mt][nt][0], acc[mt][nt][1]);
            if (r0 + 8 < M)
                *(__half2*)&outp[(size_t)(r0 + 8) * 128 + col] =
                    __floats2half2_rn(acc[mt][nt][2], acc[mt][nt][3]);
        }
    }
}

// ---------------- aggregation + pooling (+ next-layer A write) ----------------
#define GNODES 16
__global__ void __launch_bounds__(512)
gather_combine(const float* __restrict__ b, const int* __restrict__ batch,
               int layer, int write_a) {
    __shared__ float sv[GNODES][CONV_OUT];
    __shared__ int   sbat[GNODES];

    int tid = threadIdx.x;
    int wid = tid >> 5;
    int lane = tid & 31;
    int node = blockIdx.x * GNODES + wid;
    bool valid = (node < N_NODES);

    if (valid) {
        int s0 = d_rowptr[node];
        int s1 = d_rowptr[node + 1];

        float acc0 = 0.f, acc1 = 0.f, acc2 = 0.f, acc3 = 0.f;
#pragma unroll 4
        for (int j = s0; j < s1; j++) {
            int nb = d_adj[j];
            uint2 v = *(const uint2*)&d_projLh[(size_t)nb * 128 + lane * 4];
            float2 f0 = __half22float2(*(__half2*)&v.x);
            float2 f1 = __half22float2(*(__half2*)&v.y);
            acc0 += f0.x; acc1 += f0.y; acc2 += f1.x; acc3 += f1.y;
        }
        float inv = 1.0f / fmaxf((float)(s1 - s0), 1.0f);
        uint2 rv = *(const uint2*)&d_projRh[(size_t)node * 128 + lane * 4];
        float2 r0 = __half22float2(*(__half2*)&rv.x);
        float2 r1 = __half22float2(*(__half2*)&rv.y);
        float4 bb = *(const float4*)&b[lane * 4];
        float hv[4];
        hv[0] = acc0 * inv + r0.x + bb.x;
        hv[1] = acc1 * inv + r0.y + bb.y;
        hv[2] = acc2 * inv + r1.x + bb.z;
        hv[3] = acc3 * inv + r1.y + bb.w;

        if (write_a) {
            __half2 h0 = __floats2half2_rn(hv[0], hv[1]);
            __half2 h1 = __floats2half2_rn(hv[2], hv[3]);
            size_t off = (size_t)node * STRIDE12 + lane * 4;
            *(__half2*)&d_A12[off]     = h0;
            *(__half2*)&d_A12[off + 2] = h1;
        }

        *(float4*)&sv[wid][lane * 4] = make_float4(hv[0], hv[1], hv[2], hv[3]);
        if (lane == 0) sbat[wid] = batch[node];
    } else {
        if (lane == 0) sbat[wid] = -1;
    }
    __syncthreads();

    if (tid < CONV_OUT) {
        int col = tid;
        int cur = -1;
        float mx = 0.f;
#pragma unroll
        for (int i = 0; i < GNODES; i++) {
            int bt = sbat[i];
            if (bt != cur) {
                if (cur >= 0)
                    atomicMax(&d_genc[cur * HCAT + layer * 128 + col], encf(mx));
                cur = bt;
                mx = -3.4e38f;
            }
            if (bt >= 0) mx = fmaxf(mx, sv[i][col]);
        }
        if (cur >= 0)
            atomicMax(&d_genc[cur * HCAT + layer * 128 + col], encf(mx));
    }
}

// ---------------- FC head ----------------
__global__ void fc_kernel(const float* __restrict__ Wfc1, const float* __restrict__ bfc1,
                          const float* __restrict__ Wfc2, const float* __restrict__ bfc2,
                          float* __restrict__ out) {
    __shared__ float g[HCAT];
    __shared__ float z[160];
    int gr = blockIdx.x, t = threadIdx.x;

    for (int i = t; i < HCAT; i += 160) g[i] = decf(d_genc[gr * HCAT + i]);
    __syncthreads();

    float acc = bfc1[t];
#pragma unroll 8
    for (int k = 0; k < HCAT; k++) acc += g[k] * Wfc1[k * 160 + t];
    z[t] = fmaxf(acc, 0.f);
    __syncthreads();

    if (t < 10) {
        float o = bfc2[t];
#pragma unroll 8
        for (int k = 0; k < 160; k++) o += z[k] * Wfc2[k * 10 + t];
        out[gr * 10 + t] = o;
    }
}

// ---------------- launch ----------------
extern "C" void kernel_launch(void* const* d_in, const int* in_sizes, int n_in,
                              void* d_out, int out_size) {
    const float* x     = (const float*)d_in[0];
    const int*   eidx  = (const int*)d_in[1];
    const int*   batch = (const int*)d_in[2];
    const float* info  = (const float*)d_in[3];
    const float* Wl[3] = { (const float*)d_in[4], (const float*)d_in[7],  (const float*)d_in[10] };
    const float* Wr[3] = { (const float*)d_in[5], (const float*)d_in[8],  (const float*)d_in[11] };
    const float* bb[3] = { (const float*)d_in[6], (const float*)d_in[9],  (const float*)d_in[12] };
    const float* Wfc1  = (const float*)d_in[13];
    const float* bfc1  = (const float*)d_in[14];
    const float* Wfc2  = (const float*)d_in[15];
    const float* bfc2  = (const float*)d_in[16];
    float* out = (float*)d_out;

    const int* src = eidx;
    const int* dst = eidx + N_EDGES;
    const int T = 256;

    cudaFuncSetAttribute(sage_gemm, cudaFuncAttributeMaxDynamicSharedMemorySize, SM_TOTAL);

    prep_fused<<<(int)((PREP_TOTAL + T - 1) / T), T>>>(x, info, batch,
        Wl[0], Wr[0], Wl[1], Wr[1], Wl[2], Wr[2]);
    deg_kernel<<<(N_EDGES / 4 + T - 1) / T, T>>>(dst);
    scan_kernel<<<1, 1024>>>();
    fill_kernel<<<(N_EDGES / 4 + T - 1) / T, T>>>(src, dst);

    __half *a0 = nullptr, *a12 = nullptr, *bp = nullptr;
    cudaGetSymbolAddress((void**)&a0, d_A0);
    cudaGetSymbolAddress((void**)&a12, d_A12);
    cudaGetSymbolAddress((void**)&bp, d_B);

    for (int layer = 0; layer < 3; layer++) {
        int K = (layer == 0) ? 128 : 160;
        int nch = K / 32;
        const __half* A = (layer == 0) ? a0 : a12;
        int strideA = (layer == 0) ? 128 : STRIDE12;

        sage_gemm<<<dim3((N_NODES + 127) / 128, 2), 256, SM_TOTAL>>>(
            A, bp + layer * 256 * KPAD, strideA, nch);

        gather_combine<<<(N_NODES + GNODES - 1) / GNODES, 512>>>(bb[layer], batch, layer, layer < 2);
    }

    fc_kernel<<<NUM_GRAPHS, 160>>>(Wfc1, bfc1, Wfc2, bfc2, out);
    (void)in_sizes; (void)n_in; (void)out_size;
}